// round 5
// baseline (speedup 1.0000x reference)
#include <cuda_runtime.h>

#define P_N 200000
#define C_N 50000
#define L_N 8
#define F_N 32
#define DIN 64
#define NSTEPS 5

#define PB_BLOCKS ((P_N + 255) / 256)   // 782
#define CB_BLOCKS ((C_N + 255) / 256)   // 196
#define SCAN_TILE 64
#define PST 66                          // u64 stride (64 + 2 pad)

typedef unsigned long long u64;

// ---------------- device scratch ----------------
__device__ float g_p[(size_t)P_N * F_N];
__device__ int   g_order[P_N];
__device__ int   g_idx[(size_t)P_N * L_N];
__device__ int   g_len[P_N];
__device__ float g_agg[(size_t)C_N * F_N];
__device__ float g_table[(size_t)C_N * 96];
__device__ int   g_cnt[16];
__device__ int   g_blkhist[PB_BLOCKS * 8];
__device__ int   g_done;

// ---------------- helpers ----------------
__device__ __forceinline__ u64 ffma2(u64 a, u64 b, u64 c) {
    u64 d;
    asm("fma.rn.f32x2 %0, %1, %2, %3;" : "=l"(d) : "l"(a), "l"(b), "l"(c));
    return d;
}
__device__ __forceinline__ float2 u2f(u64 v) {
    float2 r;
    asm("mov.b64 {%0,%1}, %2;" : "=f"(r.x), "=f"(r.y) : "l"(v));
    return r;
}
__device__ __forceinline__ u64 f2u(float a, float b) {
    u64 r;
    asm("mov.b64 %0, {%1,%2};" : "=l"(r) : "f"(a), "f"(b));
    return r;
}
__device__ __forceinline__ float hsum(u64 v) { float2 f = u2f(v); return f.x + f.y; }

__device__ __forceinline__ float tanh_ap(float x) {
    float y;
    asm("tanh.approx.f32 %0, %1;" : "=f"(y) : "f"(x));
    return y;
}
__device__ __forceinline__ float fast_sigmoid(float v) {
    return fmaf(0.5f, tanh_ap(0.5f * v), 0.5f);
}
__device__ __forceinline__ float fast_tanh(float v) { return tanh_ap(v); }

__device__ __forceinline__ void red_add_v4(float* p, float4 v) {
    asm volatile("red.global.add.v4.f32 [%0], {%1,%2,%3,%4};"
                 :: "l"(p), "f"(v.x), "f"(v.y), "f"(v.z), "f"(v.w) : "memory");
}
__device__ __forceinline__ u64 ldg64(const u64* p) {
    u64 v;
    asm("ld.global.nc.b64 %0, [%1];" : "=l"(v) : "l"(p));
    return v;
}

// ---------------- fused hist + prefix (last-block-done) ----------------
__global__ void __launch_bounds__(256) hist_prefix_kernel(const int* __restrict__ plen) {
    __shared__ int lh[8];
    __shared__ int slast;
    int tid = threadIdx.x;
    if (tid < 8) lh[tid] = 0;
    __syncthreads();
    int i = blockIdx.x * 256 + tid;
    if (i < P_N) {
        int b = plen[i]; b = b < 0 ? 0 : (b > 7 ? 7 : b);
        atomicAdd(&lh[b], 1);
    }
    __syncthreads();
    if (tid < 8) g_blkhist[blockIdx.x * 8 + tid] = lh[tid];
    __threadfence();
    if (tid == 0) {
        int t = atomicAdd(&g_done, 1);
        slast = (t == gridDim.x - 1) ? 1 : 0;
    }
    __syncthreads();
    if (slast) {
        __threadfence();
        int local[8] = {0, 0, 0, 0, 0, 0, 0, 0};
        for (int j = tid; j < PB_BLOCKS; j += 256) {
#pragma unroll
            for (int b = 0; b < 8; b++) local[b] += g_blkhist[j * 8 + b];
        }
        if (tid < 8) lh[tid] = 0;
        __syncthreads();
#pragma unroll
        for (int b = 0; b < 8; b++) atomicAdd(&lh[b], local[b]);
        __syncthreads();
        if (tid == 0) {
            int acc = 0;
#pragma unroll
            for (int b = 7; b >= 0; b--) { int cv = lh[b]; g_cnt[b] = acc; acc += cv; }
            g_done = 0;   // reset for next replay
        }
    }
}

__global__ void __launch_bounds__(256) scatter_kernel(const int* __restrict__ plen) {
    int i = blockIdx.x * 256 + threadIdx.x;
    if (i < P_N) {
        int b = plen[i]; b = b < 0 ? 0 : (b > 7 ? 7 : b);
        int pos = atomicAdd(&g_cnt[b], 1);
        g_order[pos] = i;
    }
}

// ---------------- fused build(paths) + initc + step0 gi1 table (channels) ----------------
__global__ void __launch_bounds__(256) buildinit_gi_kernel(const int* __restrict__ plen,
                                                           const int* __restrict__ pci,
                                                           const float* __restrict__ praw,
                                                           const float* __restrict__ craw,
                                                           const float* __restrict__ Wp,
                                                           const float* __restrict__ bp,
                                                           const float* __restrict__ Wc,
                                                           const float* __restrict__ bc,
                                                           const float* __restrict__ Wi1,
                                                           const float* __restrict__ bi1,
                                                           const float* __restrict__ bh1,
                                                           float* __restrict__ c)
{
    __shared__ __align__(16) float sWt[F_N * DIN];    // init weights transposed [f][d]
    __shared__ float sb[F_N];
    __shared__ __align__(16) float sWi1f[96 * 32];    // raw Wi1 for table part
    __shared__ float sb1[96];
    int tid = threadIdx.x;
    bool isPath = blockIdx.x < PB_BLOCKS;
    const float* W = isPath ? Wp : Wc;
    const float* b = isPath ? bp : bc;
    for (int i = tid; i < DIN * F_N; i += 256) {
        int d = i >> 5, f = i & 31;
        sWt[f * DIN + d] = W[i];
    }
    if (tid < F_N) sb[tid] = b[tid];
    if (!isPath) {
        for (int i = tid; i < 96 * 32; i += 256) sWi1f[i] = Wi1[i];
        if (tid < 96) sb1[tid] = bi1[tid] + (tid < 64 ? bh1[tid] : 0.0f);
    }
    __syncthreads();

    int row, srcrow;
    const float* xsrc;
    float* dst;
    if (isPath) {
        row = blockIdx.x * 256 + tid;
        if (row >= P_N) return;
        srcrow = g_order[row];
        g_len[row] = plen[srcrow];
        const int4* si = (const int4*)(pci + (size_t)srcrow * L_N);
        int4* di = (int4*)(g_idx + (size_t)row * L_N);
        di[0] = si[0]; di[1] = si[1];
        xsrc = praw;
        dst = g_p + (size_t)row * F_N;
    } else {
        row = (blockIdx.x - PB_BLOCKS) * 256 + tid;
        if (row >= C_N) return;
        srcrow = row;
        xsrc = craw;
        dst = c + (size_t)row * F_N;
    }

    u64 x2[32];
    const ulonglong2* xg = (const ulonglong2*)(xsrc + (size_t)srcrow * DIN);
#pragma unroll
    for (int q = 0; q < 16; q++) { ulonglong2 v = xg[q]; x2[2 * q] = v.x; x2[2 * q + 1] = v.y; }
    const u64* wt = (const u64*)sWt;
    float cr[32];
    for (int f0 = 0; f0 < F_N; f0 += 4) {
        u64 a0 = 0, a1 = 0, a2 = 0, a3 = 0;
        const u64* w0 = wt + (f0 + 0) * 32;
        const u64* w1 = wt + (f0 + 1) * 32;
        const u64* w2 = wt + (f0 + 2) * 32;
        const u64* w3 = wt + (f0 + 3) * 32;
#pragma unroll
        for (int k = 0; k < 32; k++) {
            a0 = ffma2(x2[k], w0[k], a0);
            a1 = ffma2(x2[k], w1[k], a1);
            a2 = ffma2(x2[k], w2[k], a2);
            a3 = ffma2(x2[k], w3[k], a3);
        }
        cr[f0 + 0] = fmaxf(hsum(a0) + sb[f0 + 0], 0.0f);
        cr[f0 + 1] = fmaxf(hsum(a1) + sb[f0 + 1], 0.0f);
        cr[f0 + 2] = fmaxf(hsum(a2) + sb[f0 + 2], 0.0f);
        cr[f0 + 3] = fmaxf(hsum(a3) + sb[f0 + 3], 0.0f);
    }
    float4* out4 = (float4*)dst;
#pragma unroll
    for (int q = 0; q < 8; q++)
        out4[q] = make_float4(cr[4 * q], cr[4 * q + 1], cr[4 * q + 2], cr[4 * q + 3]);

    if (!isPath) {
        // zero agg row for step 0
        float4 z4 = make_float4(0.f, 0.f, 0.f, 0.f);
        float4* ag = (float4*)(g_agg + (size_t)row * F_N);
#pragma unroll
        for (int q = 0; q < 8; q++) ag[q] = z4;
        // table row = cr @ Wi1^T + bi1 (+bh1 folded for r,z)
        u64 xc[16];
#pragma unroll
        for (int k = 0; k < 16; k++) xc[k] = f2u(cr[2 * k], cr[2 * k + 1]);
        u64* trow = (u64*)(g_table + (size_t)row * 96);
        for (int f0 = 0; f0 < 96; f0 += 2) {
            const u64* wr0 = (const u64*)(sWi1f + (f0 + 0) * 32);
            const u64* wr1 = (const u64*)(sWi1f + (f0 + 1) * 32);
            u64 a0 = 0, a1 = 0;
#pragma unroll
            for (int k = 0; k < 16; k++) {
                a0 = ffma2(xc[k], wr0[k], a0);
                a1 = ffma2(xc[k], wr1[k], a1);
            }
            int gate = f0 >> 5, fin = f0 & 31;
            trow[gate * 16 + (fin >> 1)] = f2u(hsum(a0) + sb1[f0], hsum(a1) + sb1[f0 + 1]);
        }
    }
}

// ---------------- GEMM-tiled fused scan (double-buffered h, 1 sync/substep) ----------------
// Block: 64 paths x 96 outs, 256 threads = 32(px) x 8(fy), thread tile 2 paths x 12 outs.
__global__ void __launch_bounds__(256) scan3_kernel(const float* __restrict__ Wh,
                                                    const float* __restrict__ bh,
                                                    float* __restrict__ final_out)
{
    __shared__ __align__(16) u64 sww[32 * 48];        // [k][po] weight pairs
    __shared__ __align__(16) u64 shh[2 * 32 * PST];   // double buffer [k][p] (h,h)
    __shared__ int sidx[SCAN_TILE * L_N];
    __shared__ int slen[SCAN_TILE];
    __shared__ float sbhn[32];

    int tid = threadIdx.x;
    int s0 = blockIdx.x * SCAN_TILE;
    int pcount = min(SCAN_TILE, P_N - s0);

    for (int i = tid; i < 32 * 48; i += 256) {
        int k = i / 48, po = i % 48;
        sww[k * 48 + po] = f2u(Wh[(2 * po) * 32 + k], Wh[(2 * po + 1) * 32 + k]);
    }
    if (tid < 32) sbhn[tid] = bh[64 + tid];
    for (int i = tid; i < pcount * 2; i += 256)
        ((int4*)sidx)[i] = ((const int4*)(g_idx + (size_t)s0 * L_N))[i];
    if (tid < pcount) slen[tid] = g_len[s0 + tid];
    if (pcount < SCAN_TILE) {
        for (int i = tid; i < 32 * SCAN_TILE; i += 256) {
            int p = i & (SCAN_TILE - 1);
            if (p >= pcount) {
                shh[(i >> 6) * PST + p] = 0ull;
                shh[32 * PST + (i >> 6) * PST + p] = 0ull;
            }
        }
    }
    for (int i = tid; i < pcount * 8; i += 256) {
        int p = i >> 3, kq = i & 7;
        float4 v = ((const float4*)(g_p + (size_t)s0 * F_N))[i];
        shh[(4 * kq + 0) * PST + p] = f2u(v.x, v.x);
        shh[(4 * kq + 1) * PST + p] = f2u(v.y, v.y);
        shh[(4 * kq + 2) * PST + p] = f2u(v.z, v.z);
        shh[(4 * kq + 3) * PST + p] = f2u(v.w, v.w);
    }
    __syncthreads();

    int tmax = slen[0];       // descending sort => block max
    int px = tid >> 3;        // 0..31
    int fy = tid & 7;         // 0..7
    int pbase = px * 2;
    int cur = 0;

    for (int t = 0; t <= tmax; t++) {
        u64* bufc = shh + cur * (32 * PST);
        u64* bufn = shh + (cur ^ 1) * (32 * PST);
        u64 acc[6][2];
#pragma unroll
        for (int g = 0; g < 6; g++) { acc[g][0] = 0ull; acc[g][1] = 0ull; }

#pragma unroll 4
        for (int k = 0; k < 32; k++) {
            const ulonglong2* wrow = (const ulonglong2*)(sww + k * 48);
            ulonglong2 wr = wrow[fy];
            ulonglong2 wz = wrow[8 + fy];
            ulonglong2 wn = wrow[16 + fy];
            ulonglong2 h01 = *(const ulonglong2*)(bufc + k * PST + pbase);
            u64 hp[2] = {h01.x, h01.y};
#pragma unroll
            for (int p = 0; p < 2; p++) {
                acc[0][p] = ffma2(hp[p], wr.x, acc[0][p]);
                acc[1][p] = ffma2(hp[p], wr.y, acc[1][p]);
                acc[2][p] = ffma2(hp[p], wz.x, acc[2][p]);
                acc[3][p] = ffma2(hp[p], wz.y, acc[3][p]);
                acc[4][p] = ffma2(hp[p], wn.x, acc[4][p]);
                acc[5][p] = ffma2(hp[p], wn.y, acc[5][p]);
            }
        }

        // epilogue: write next buffer (no sync needed vs k-loop reads of cur)
#pragma unroll
        for (int p = 0; p < 2; p++) {
            int pp = pbase + p;
            bool active = (pp < pcount) && (t <= slen[pp]);
            if (active) {
                int ch = sidx[pp * L_N + t];
                const u64* tgp = (const u64*)(g_table + (size_t)ch * 96);
#pragma unroll
                for (int q = 0; q < 2; q++) {
                    float2 gr = u2f(ldg64(tgp + 2 * fy + q));
                    float2 gz = u2f(ldg64(tgp + 16 + 2 * fy + q));
                    float2 gn = u2f(ldg64(tgp + 32 + 2 * fy + q));
                    float2 vr = u2f(acc[0 + q][p]);
                    float2 vz = u2f(acc[2 + q][p]);
                    float2 vn = u2f(acc[4 + q][p]);
#pragma unroll
                    for (int half = 0; half < 2; half++) {
                        int f = 4 * fy + 2 * q + half;
                        float ivr = half ? vr.y : vr.x;
                        float ivz = half ? vz.y : vz.x;
                        float ivn = half ? vn.y : vn.x;
                        float igr = half ? gr.y : gr.x;
                        float igz = half ? gz.y : gz.x;
                        float ign = half ? gn.y : gn.x;
                        float r = fast_sigmoid(igr + ivr);
                        float z = fast_sigmoid(igz + ivz);
                        float n = fast_tanh(ign + r * (ivn + sbhn[f]));
                        float hold = *((const float*)(bufc + f * PST + pp));
                        float hnew = n + z * (hold - n);
                        bufn[f * PST + pp] = f2u(hnew, hnew);
                    }
                }
            } else {
#pragma unroll
                for (int j = 0; j < 4; j++) {
                    int f = 4 * fy + j;
                    bufn[f * PST + pp] = bufc[f * PST + pp];
                }
            }
        }
        __syncthreads();
        cur ^= 1;
    }

    // tail: write back p (to g_p, or scattered to final out) + segment-sum atomics
    u64* buff = shh + cur * (32 * PST);
    if (tid < 2 * SCAN_TILE) {
        int p = tid & (SCAN_TILE - 1);
        int kc = tid >> 6;      // 0 or 1
        if (p < pcount) {
            float v[16];
#pragma unroll
            for (int j = 0; j < 16; j++)
                v[j] = *((const float*)(buff + (kc * 16 + j) * PST + p));
            float4* dst;
            if (final_out) {
                int ord = g_order[s0 + p];
                dst = (float4*)(final_out + (size_t)ord * F_N + kc * 16);
            } else {
                dst = (float4*)(g_p + (size_t)(s0 + p) * F_N + kc * 16);
            }
#pragma unroll
            for (int q = 0; q < 4; q++)
                dst[q] = make_float4(v[4 * q], v[4 * q + 1], v[4 * q + 2], v[4 * q + 3]);
            int ln = slen[p];
#pragma unroll 1
            for (int t = 0; t <= ln; t++) {
                int ch = sidx[p * L_N + t];
                float* base = g_agg + (size_t)ch * F_N + kc * 16;
                red_add_v4(base + 0,  make_float4(v[0],  v[1],  v[2],  v[3]));
                red_add_v4(base + 4,  make_float4(v[4],  v[5],  v[6],  v[7]));
                red_add_v4(base + 8,  make_float4(v[8],  v[9],  v[10], v[11]));
                red_add_v4(base + 12, make_float4(v[12], v[13], v[14], v[15]));
            }
        }
    }
}

// ---------------- fused layer2: c = GRU(agg, c); optionally gi1 table for next step ----------------
// Block: 64 channels, 256 threads = 32(px) x 8(fy), thread tile 2 ch x 12 outs.
__global__ void __launch_bounds__(256) layer2_kernel(float* __restrict__ c,
                                                     const float* __restrict__ Wi2,
                                                     const float* __restrict__ Wh2,
                                                     const float* __restrict__ bi2,
                                                     const float* __restrict__ bh2,
                                                     const float* __restrict__ Wi1,
                                                     const float* __restrict__ bi1,
                                                     const float* __restrict__ bh1,
                                                     int want_table)
{
    __shared__ __align__(16) u64 swa[32 * 48];     // Wi2 pairs, later Wi1 pairs
    __shared__ __align__(16) u64 swh[32 * 48];     // Wh2 pairs
    __shared__ __align__(16) u64 sbuf[32 * PST];   // staging: agg -> c -> cnew (dup)
    __shared__ float sbi[96];                      // bi2 (+bh2 for r,z)
    __shared__ float sbhn2[32];                    // bh2_n
    __shared__ float sb1[96];                      // bi1 (+bh1 for r,z)

    int tid = threadIdx.x;
    int s0 = blockIdx.x * SCAN_TILE;
    int rcount = min(SCAN_TILE, C_N - s0);

    for (int i = tid; i < 32 * 48; i += 256) {
        int k = i / 48, po = i % 48;
        swa[k * 48 + po] = f2u(Wi2[(2 * po) * 32 + k], Wi2[(2 * po + 1) * 32 + k]);
        swh[k * 48 + po] = f2u(Wh2[(2 * po) * 32 + k], Wh2[(2 * po + 1) * 32 + k]);
    }
    if (tid < 96) {
        sbi[tid] = bi2[tid] + (tid < 64 ? bh2[tid] : 0.0f);
        sb1[tid] = bi1[tid] + (tid < 64 ? bh1[tid] : 0.0f);
    }
    if (tid < 32) sbhn2[tid] = bh2[64 + tid];
    if (rcount < SCAN_TILE) {
        for (int i = tid; i < 32 * SCAN_TILE; i += 256) {
            int p = i & (SCAN_TILE - 1);
            if (p >= rcount) sbuf[(i >> 6) * PST + p] = 0ull;
        }
    }
    // stage agg rows (dup), then zero them (same-thread mapping => safe)
    for (int i = tid; i < rcount * 8; i += 256) {
        int p = i >> 3, kq = i & 7;
        float4 v = ((const float4*)(g_agg + (size_t)s0 * F_N))[i];
        sbuf[(4 * kq + 0) * PST + p] = f2u(v.x, v.x);
        sbuf[(4 * kq + 1) * PST + p] = f2u(v.y, v.y);
        sbuf[(4 * kq + 2) * PST + p] = f2u(v.z, v.z);
        sbuf[(4 * kq + 3) * PST + p] = f2u(v.w, v.w);
        ((float4*)(g_agg + (size_t)s0 * F_N))[i] = make_float4(0.f, 0.f, 0.f, 0.f);
    }
    __syncthreads();

    int px = tid >> 3, fy = tid & 7;
    int pbase = px * 2;

    u64 acc_i[6][2];
#pragma unroll
    for (int g = 0; g < 6; g++) { acc_i[g][0] = 0ull; acc_i[g][1] = 0ull; }
#pragma unroll 4
    for (int k = 0; k < 32; k++) {
        const ulonglong2* wrow = (const ulonglong2*)(swa + k * 48);
        ulonglong2 wr = wrow[fy];
        ulonglong2 wz = wrow[8 + fy];
        ulonglong2 wn = wrow[16 + fy];
        ulonglong2 h01 = *(const ulonglong2*)(sbuf + k * PST + pbase);
        u64 hp[2] = {h01.x, h01.y};
#pragma unroll
        for (int p = 0; p < 2; p++) {
            acc_i[0][p] = ffma2(hp[p], wr.x, acc_i[0][p]);
            acc_i[1][p] = ffma2(hp[p], wr.y, acc_i[1][p]);
            acc_i[2][p] = ffma2(hp[p], wz.x, acc_i[2][p]);
            acc_i[3][p] = ffma2(hp[p], wz.y, acc_i[3][p]);
            acc_i[4][p] = ffma2(hp[p], wn.x, acc_i[4][p]);
            acc_i[5][p] = ffma2(hp[p], wn.y, acc_i[5][p]);
        }
    }
    __syncthreads();

    // restage: sbuf <- c rows (dup); swa <- Wi1 pairs (for table k-loop)
    for (int i = tid; i < rcount * 8; i += 256) {
        int p = i >> 3, kq = i & 7;
        float4 v = ((const float4*)(c + (size_t)s0 * F_N))[i];
        sbuf[(4 * kq + 0) * PST + p] = f2u(v.x, v.x);
        sbuf[(4 * kq + 1) * PST + p] = f2u(v.y, v.y);
        sbuf[(4 * kq + 2) * PST + p] = f2u(v.z, v.z);
        sbuf[(4 * kq + 3) * PST + p] = f2u(v.w, v.w);
    }
    if (want_table) {
        for (int i = tid; i < 32 * 48; i += 256) {
            int k = i / 48, po = i % 48;
            swa[k * 48 + po] = f2u(Wi1[(2 * po) * 32 + k], Wi1[(2 * po + 1) * 32 + k]);
        }
    }
    __syncthreads();

    u64 acc_h[6][2];
#pragma unroll
    for (int g = 0; g < 6; g++) { acc_h[g][0] = 0ull; acc_h[g][1] = 0ull; }
#pragma unroll 4
    for (int k = 0; k < 32; k++) {
        const ulonglong2* wrow = (const ulonglong2*)(swh + k * 48);
        ulonglong2 wr = wrow[fy];
        ulonglong2 wz = wrow[8 + fy];
        ulonglong2 wn = wrow[16 + fy];
        ulonglong2 h01 = *(const ulonglong2*)(sbuf + k * PST + pbase);
        u64 hp[2] = {h01.x, h01.y};
#pragma unroll
        for (int p = 0; p < 2; p++) {
            acc_h[0][p] = ffma2(hp[p], wr.x, acc_h[0][p]);
            acc_h[1][p] = ffma2(hp[p], wr.y, acc_h[1][p]);
            acc_h[2][p] = ffma2(hp[p], wz.x, acc_h[2][p]);
            acc_h[3][p] = ffma2(hp[p], wz.y, acc_h[3][p]);
            acc_h[4][p] = ffma2(hp[p], wn.x, acc_h[4][p]);
            acc_h[5][p] = ffma2(hp[p], wn.y, acc_h[5][p]);
        }
    }
    __syncthreads();   // all k-loop reads of sbuf done before in-place cnew writes

    // epilogue: cnew -> c global + sbuf in-place (dup) for table k-loop
#pragma unroll
    for (int p = 0; p < 2; p++) {
        int pp = pbase + p;
        if (pp < rcount) {
            int ch = s0 + pp;
            u64* cdst = (u64*)(c + (size_t)ch * F_N);
#pragma unroll
            for (int q = 0; q < 2; q++) {
                float2 vi_r = u2f(acc_i[0 + q][p]);
                float2 vi_z = u2f(acc_i[2 + q][p]);
                float2 vi_n = u2f(acc_i[4 + q][p]);
                float2 vh_r = u2f(acc_h[0 + q][p]);
                float2 vh_z = u2f(acc_h[2 + q][p]);
                float2 vh_n = u2f(acc_h[4 + q][p]);
                float hnew2[2];
#pragma unroll
                for (int half = 0; half < 2; half++) {
                    int f = 4 * fy + 2 * q + half;
                    float ir = half ? vi_r.y : vi_r.x;
                    float iz = half ? vi_z.y : vi_z.x;
                    float in_ = half ? vi_n.y : vi_n.x;
                    float hr = half ? vh_r.y : vh_r.x;
                    float hz = half ? vh_z.y : vh_z.x;
                    float hn = half ? vh_n.y : vh_n.x;
                    float r = fast_sigmoid(ir + sbi[f] + hr);
                    float z = fast_sigmoid(iz + sbi[32 + f] + hz);
                    float n = fast_tanh(in_ + sbi[64 + f] + r * (hn + sbhn2[f]));
                    float hold = *((const float*)(sbuf + f * PST + pp));
                    float hv = n + z * (hold - n);
                    hnew2[half] = hv;
                    sbuf[f * PST + pp] = f2u(hv, hv);
                }
                cdst[2 * fy + q] = f2u(hnew2[0], hnew2[1]);
            }
        }
    }

    if (!want_table) return;
    __syncthreads();   // cnew staged

    u64 acc[6][2];
#pragma unroll
    for (int g = 0; g < 6; g++) { acc[g][0] = 0ull; acc[g][1] = 0ull; }
#pragma unroll 4
    for (int k = 0; k < 32; k++) {
        const ulonglong2* wrow = (const ulonglong2*)(swa + k * 48);
        ulonglong2 wr = wrow[fy];
        ulonglong2 wz = wrow[8 + fy];
        ulonglong2 wn = wrow[16 + fy];
        ulonglong2 h01 = *(const ulonglong2*)(sbuf + k * PST + pbase);
        u64 hp[2] = {h01.x, h01.y};
#pragma unroll
        for (int p = 0; p < 2; p++) {
            acc[0][p] = ffma2(hp[p], wr.x, acc[0][p]);
            acc[1][p] = ffma2(hp[p], wr.y, acc[1][p]);
            acc[2][p] = ffma2(hp[p], wz.x, acc[2][p]);
            acc[3][p] = ffma2(hp[p], wz.y, acc[3][p]);
            acc[4][p] = ffma2(hp[p], wn.x, acc[4][p]);
            acc[5][p] = ffma2(hp[p], wn.y, acc[5][p]);
        }
    }
#pragma unroll
    for (int p = 0; p < 2; p++) {
        int pp = pbase + p;
        if (pp < rcount) {
            u64* trow = (u64*)(g_table + (size_t)(s0 + pp) * 96);
#pragma unroll
            for (int gate = 0; gate < 3; gate++) {
#pragma unroll
                for (int q = 0; q < 2; q++) {
                    int fb = 4 * fy + 2 * q;
                    float2 a = u2f(acc[2 * gate + q][p]);
                    trow[gate * 16 + 2 * fy + q] =
                        f2u(a.x + sb1[gate * 32 + fb], a.y + sb1[gate * 32 + fb + 1]);
                }
            }
        }
    }
}

// ---------------- launch ----------------
extern "C" void kernel_launch(void* const* d_in, const int* in_sizes, int n_in,
                              void* d_out, int out_size)
{
    const float* path_raw    = (const float*)d_in[0];
    const float* channel_raw = (const float*)d_in[1];
    const int*   pci         = (const int*)d_in[2];
    const int*   plen        = (const int*)d_in[3];
    // d_in[4] = num_steps (constant 5)
    const float* Wp  = (const float*)d_in[5];
    const float* bp  = (const float*)d_in[6];
    const float* Wc  = (const float*)d_in[7];
    const float* bc  = (const float*)d_in[8];
    const float* Wi1 = (const float*)d_in[9];
    const float* Wh1 = (const float*)d_in[10];
    const float* bi1 = (const float*)d_in[11];
    const float* bh1 = (const float*)d_in[12];
    const float* Wi2 = (const float*)d_in[13];
    const float* Wh2 = (const float*)d_in[14];
    const float* bi2 = (const float*)d_in[15];
    const float* bh2 = (const float*)d_in[16];

    float* outp = (float*)d_out;
    float* c    = outp + (size_t)P_N * F_N;

    int gridScan = (P_N + SCAN_TILE - 1) / SCAN_TILE;   // 3125
    int gridL2   = (C_N + SCAN_TILE - 1) / SCAN_TILE;   // 782

    hist_prefix_kernel<<<PB_BLOCKS, 256>>>(plen);
    scatter_kernel<<<PB_BLOCKS, 256>>>(plen);
    buildinit_gi_kernel<<<PB_BLOCKS + CB_BLOCKS, 256>>>(plen, pci, path_raw, channel_raw,
                                                        Wp, bp, Wc, bc, Wi1, bi1, bh1, c);
    for (int st = 0; st < NSTEPS; st++) {
        scan3_kernel<<<gridScan, 256>>>(Wh1, bh1, (st == NSTEPS - 1) ? outp : nullptr);
        layer2_kernel<<<gridL2, 256>>>(c, Wi2, Wh2, bi2, bh2, Wi1, bi1, bh1,
                                       (st < NSTEPS - 1) ? 1 : 0);
    }
}

// round 6
// speedup vs baseline: 1.1537x; 1.1537x over previous
#include <cuda_runtime.h>

#define P_N 200000
#define C_N 50000
#define L_N 8
#define F_N 32
#define DIN 64
#define NSTEPS 5

#define PB_BLOCKS ((P_N + 255) / 256)   // 782
#define CB_BLOCKS ((C_N + 255) / 256)   // 196

#define STILE 256                       // scan paths per block
#define PS 264                          // float stride of shf rows (mult of 4)
#define L2TILE 64
#define PST 66                          // u64 stride for layer2 staging

typedef unsigned long long u64;

// ---------------- device scratch ----------------
__device__ float g_p[(size_t)P_N * F_N];
__device__ int   g_order[P_N];
__device__ int   g_idx[(size_t)P_N * L_N];
__device__ int   g_len[P_N];
__device__ float g_agg[(size_t)C_N * F_N];
__device__ float g_table[(size_t)C_N * 96];
__device__ int   g_cnt[16];
__device__ int   g_blkhist[PB_BLOCKS * 8];
__device__ int   g_done;

// ---------------- helpers ----------------
__device__ __forceinline__ u64 ffma2(u64 a, u64 b, u64 c) {
    u64 d;
    asm("fma.rn.f32x2 %0, %1, %2, %3;" : "=l"(d) : "l"(a), "l"(b), "l"(c));
    return d;
}
__device__ __forceinline__ float2 u2f(u64 v) {
    float2 r;
    asm("mov.b64 {%0,%1}, %2;" : "=f"(r.x), "=f"(r.y) : "l"(v));
    return r;
}
__device__ __forceinline__ u64 f2u(float a, float b) {
    u64 r;
    asm("mov.b64 %0, {%1,%2};" : "=l"(r) : "f"(a), "f"(b));
    return r;
}
__device__ __forceinline__ float hsum(u64 v) { float2 f = u2f(v); return f.x + f.y; }

__device__ __forceinline__ float tanh_ap(float x) {
    float y;
    asm("tanh.approx.f32 %0, %1;" : "=f"(y) : "f"(x));
    return y;
}
__device__ __forceinline__ float fast_sigmoid(float v) {
    return fmaf(0.5f, tanh_ap(0.5f * v), 0.5f);
}
__device__ __forceinline__ float fast_tanh(float v) { return tanh_ap(v); }

__device__ __forceinline__ void red_add_v4(float* p, float4 v) {
    asm volatile("red.global.add.v4.f32 [%0], {%1,%2,%3,%4};"
                 :: "l"(p), "f"(v.x), "f"(v.y), "f"(v.z), "f"(v.w) : "memory");
}
__device__ __forceinline__ u64 ldg64(const u64* p) {
    u64 v;
    asm("ld.global.nc.b64 %0, [%1];" : "=l"(v) : "l"(p));
    return v;
}

// ---------------- fused hist + prefix (last-block-done) ----------------
__global__ void __launch_bounds__(256) hist_prefix_kernel(const int* __restrict__ plen) {
    __shared__ int lh[8];
    __shared__ int slast;
    int tid = threadIdx.x;
    if (tid < 8) lh[tid] = 0;
    __syncthreads();
    int i = blockIdx.x * 256 + tid;
    if (i < P_N) {
        int b = plen[i]; b = b < 0 ? 0 : (b > 7 ? 7 : b);
        atomicAdd(&lh[b], 1);
    }
    __syncthreads();
    if (tid < 8) g_blkhist[blockIdx.x * 8 + tid] = lh[tid];
    __threadfence();
    if (tid == 0) {
        int t = atomicAdd(&g_done, 1);
        slast = (t == gridDim.x - 1) ? 1 : 0;
    }
    __syncthreads();
    if (slast) {
        __threadfence();
        int local[8] = {0, 0, 0, 0, 0, 0, 0, 0};
        for (int j = tid; j < PB_BLOCKS; j += 256) {
#pragma unroll
            for (int b = 0; b < 8; b++) local[b] += g_blkhist[j * 8 + b];
        }
        if (tid < 8) lh[tid] = 0;
        __syncthreads();
#pragma unroll
        for (int b = 0; b < 8; b++) atomicAdd(&lh[b], local[b]);
        __syncthreads();
        if (tid == 0) {
            int acc = 0;
#pragma unroll
            for (int b = 7; b >= 0; b--) { int cv = lh[b]; g_cnt[b] = acc; acc += cv; }
            g_done = 0;
        }
    }
}

__global__ void __launch_bounds__(256) scatter_kernel(const int* __restrict__ plen) {
    int i = blockIdx.x * 256 + threadIdx.x;
    if (i < P_N) {
        int b = plen[i]; b = b < 0 ? 0 : (b > 7 ? 7 : b);
        int pos = atomicAdd(&g_cnt[b], 1);
        g_order[pos] = i;
    }
}

// ---------------- fused build(paths) + initc + step0 gi1 table (channels) ----------------
__global__ void __launch_bounds__(256) buildinit_gi_kernel(const int* __restrict__ plen,
                                                           const int* __restrict__ pci,
                                                           const float* __restrict__ praw,
                                                           const float* __restrict__ craw,
                                                           const float* __restrict__ Wp,
                                                           const float* __restrict__ bp,
                                                           const float* __restrict__ Wc,
                                                           const float* __restrict__ bc,
                                                           const float* __restrict__ Wi1,
                                                           const float* __restrict__ bi1,
                                                           const float* __restrict__ bh1,
                                                           float* __restrict__ c)
{
    __shared__ __align__(16) float sWt[F_N * DIN];
    __shared__ float sb[F_N];
    __shared__ __align__(16) float sWi1f[96 * 32];
    __shared__ float sb1[96];
    int tid = threadIdx.x;
    bool isPath = blockIdx.x < PB_BLOCKS;
    const float* W = isPath ? Wp : Wc;
    const float* b = isPath ? bp : bc;
    for (int i = tid; i < DIN * F_N; i += 256) {
        int d = i >> 5, f = i & 31;
        sWt[f * DIN + d] = W[i];
    }
    if (tid < F_N) sb[tid] = b[tid];
    if (!isPath) {
        for (int i = tid; i < 96 * 32; i += 256) sWi1f[i] = Wi1[i];
        if (tid < 96) sb1[tid] = bi1[tid] + (tid < 64 ? bh1[tid] : 0.0f);
    }
    __syncthreads();

    int row, srcrow;
    const float* xsrc;
    float* dst;
    if (isPath) {
        row = blockIdx.x * 256 + tid;
        if (row >= P_N) return;
        srcrow = g_order[row];
        g_len[row] = plen[srcrow];
        const int4* si = (const int4*)(pci + (size_t)srcrow * L_N);
        int4* di = (int4*)(g_idx + (size_t)row * L_N);
        di[0] = si[0]; di[1] = si[1];
        xsrc = praw;
        dst = g_p + (size_t)row * F_N;
    } else {
        row = (blockIdx.x - PB_BLOCKS) * 256 + tid;
        if (row >= C_N) return;
        srcrow = row;
        xsrc = craw;
        dst = c + (size_t)row * F_N;
    }

    u64 x2[32];
    const ulonglong2* xg = (const ulonglong2*)(xsrc + (size_t)srcrow * DIN);
#pragma unroll
    for (int q = 0; q < 16; q++) { ulonglong2 v = xg[q]; x2[2 * q] = v.x; x2[2 * q + 1] = v.y; }
    const u64* wt = (const u64*)sWt;
    float cr[32];
    for (int f0 = 0; f0 < F_N; f0 += 4) {
        u64 a0 = 0, a1 = 0, a2 = 0, a3 = 0;
        const u64* w0 = wt + (f0 + 0) * 32;
        const u64* w1 = wt + (f0 + 1) * 32;
        const u64* w2 = wt + (f0 + 2) * 32;
        const u64* w3 = wt + (f0 + 3) * 32;
#pragma unroll
        for (int k = 0; k < 32; k++) {
            a0 = ffma2(x2[k], w0[k], a0);
            a1 = ffma2(x2[k], w1[k], a1);
            a2 = ffma2(x2[k], w2[k], a2);
            a3 = ffma2(x2[k], w3[k], a3);
        }
        cr[f0 + 0] = fmaxf(hsum(a0) + sb[f0 + 0], 0.0f);
        cr[f0 + 1] = fmaxf(hsum(a1) + sb[f0 + 1], 0.0f);
        cr[f0 + 2] = fmaxf(hsum(a2) + sb[f0 + 2], 0.0f);
        cr[f0 + 3] = fmaxf(hsum(a3) + sb[f0 + 3], 0.0f);
    }
    float4* out4 = (float4*)dst;
#pragma unroll
    for (int q = 0; q < 8; q++)
        out4[q] = make_float4(cr[4 * q], cr[4 * q + 1], cr[4 * q + 2], cr[4 * q + 3]);

    if (!isPath) {
        float4 z4 = make_float4(0.f, 0.f, 0.f, 0.f);
        float4* ag = (float4*)(g_agg + (size_t)row * F_N);
#pragma unroll
        for (int q = 0; q < 8; q++) ag[q] = z4;
        u64 xc[16];
#pragma unroll
        for (int k = 0; k < 16; k++) xc[k] = f2u(cr[2 * k], cr[2 * k + 1]);
        u64* trow = (u64*)(g_table + (size_t)row * 96);
        for (int f0 = 0; f0 < 96; f0 += 2) {
            const u64* wr0 = (const u64*)(sWi1f + (f0 + 0) * 32);
            const u64* wr1 = (const u64*)(sWi1f + (f0 + 1) * 32);
            u64 a0 = 0, a1 = 0;
#pragma unroll
            for (int k = 0; k < 16; k++) {
                a0 = ffma2(xc[k], wr0[k], a0);
                a1 = ffma2(xc[k], wr1[k], a1);
            }
            int gate = f0 >> 5, fin = f0 & 31;
            trow[gate * 16 + (fin >> 1)] = f2u(hsum(a0) + sb1[f0], hsum(a1) + sb1[f0 + 1]);
        }
    }
}

// ---------------- scan4: 256 paths/block, thread tile 8 paths x 12 outs ----------------
// 256 threads = 32(px) x 8(fy). h stored NON-duplicated (float), dup in-register.
// Per k per thread: 3 LDS.128 weights + 2 LDS.128 h -> 48 FFMA2.
__global__ void __launch_bounds__(256, 1) scan4_kernel(const float* __restrict__ Wh,
                                                       const float* __restrict__ bh,
                                                       float* __restrict__ final_out)
{
    __shared__ __align__(16) u64   sww[32 * 48];     // [k][out-pair]
    __shared__ __align__(16) float shf[32 * PS];     // [k][path], plain float
    __shared__ int sidx[STILE * L_N];
    __shared__ short slen[STILE];
    __shared__ float sbhn[32];

    int tid = threadIdx.x;
    int s0 = blockIdx.x * STILE;
    int pcount = min(STILE, P_N - s0);

    for (int i = tid; i < 32 * 48; i += 256) {
        int k = i / 48, po = i % 48;
        sww[k * 48 + po] = f2u(Wh[(2 * po) * 32 + k], Wh[(2 * po + 1) * 32 + k]);
    }
    if (tid < 32) sbhn[tid] = bh[64 + tid];
    for (int i = tid; i < pcount * 2; i += 256)
        ((int4*)sidx)[i] = ((const int4*)(g_idx + (size_t)s0 * L_N))[i];
    if (tid < pcount) slen[tid] = (short)g_len[s0 + tid];
    else if (tid < STILE) slen[tid] = -1;
    if (pcount < STILE) {
        for (int i = tid; i < 32 * STILE; i += 256) {
            int p = i & (STILE - 1);
            if (p >= pcount) shf[(i >> 8) * PS + p] = 0.0f;
        }
    }
    for (int i = tid; i < pcount * 8; i += 256) {
        int p = i >> 3, kq = i & 7;
        float4 v = ((const float4*)(g_p + (size_t)s0 * F_N))[i];
        shf[(4 * kq + 0) * PS + p] = v.x;
        shf[(4 * kq + 1) * PS + p] = v.y;
        shf[(4 * kq + 2) * PS + p] = v.z;
        shf[(4 * kq + 3) * PS + p] = v.w;
    }
    __syncthreads();

    int tmax = slen[0];                 // descending sort => block max
    int px = tid >> 3;                  // 0..31
    int fy = tid & 7;                   // 0..7
    int pbase = px * 8;

    for (int t = 0; t <= tmax; t++) {
        u64 acc[6][8];
#pragma unroll
        for (int g = 0; g < 6; g++)
#pragma unroll
            for (int p = 0; p < 8; p++) acc[g][p] = 0ull;

#pragma unroll 4
        for (int k = 0; k < 32; k++) {
            const ulonglong2* wrow = (const ulonglong2*)(sww + k * 48);
            ulonglong2 wr = wrow[fy];
            ulonglong2 wz = wrow[8 + fy];
            ulonglong2 wn = wrow[16 + fy];
            const float4* hr = (const float4*)(shf + k * PS + pbase);
            float4 ha = hr[0];
            float4 hb = hr[1];
            u64 hd[8];
            hd[0] = f2u(ha.x, ha.x); hd[1] = f2u(ha.y, ha.y);
            hd[2] = f2u(ha.z, ha.z); hd[3] = f2u(ha.w, ha.w);
            hd[4] = f2u(hb.x, hb.x); hd[5] = f2u(hb.y, hb.y);
            hd[6] = f2u(hb.z, hb.z); hd[7] = f2u(hb.w, hb.w);
#pragma unroll
            for (int p = 0; p < 8; p++) {
                acc[0][p] = ffma2(hd[p], wr.x, acc[0][p]);
                acc[1][p] = ffma2(hd[p], wr.y, acc[1][p]);
                acc[2][p] = ffma2(hd[p], wz.x, acc[2][p]);
                acc[3][p] = ffma2(hd[p], wz.y, acc[3][p]);
                acc[4][p] = ffma2(hd[p], wn.x, acc[4][p]);
                acc[5][p] = ffma2(hd[p], wn.y, acc[5][p]);
            }
        }
        __syncthreads();   // k-loop reads of shf complete

        // epilogue: update h[f][p] for f = 4fy..4fy+3, p = pbase..pbase+7
#pragma unroll
        for (int p = 0; p < 8; p++) {
            int pp = pbase + p;
            if (t <= slen[pp]) {
                int ch = sidx[pp * L_N + t];
                const u64* tgp = (const u64*)(g_table + (size_t)ch * 96);
#pragma unroll
                for (int q = 0; q < 2; q++) {
                    float2 gr = u2f(ldg64(tgp + 2 * fy + q));
                    float2 gz = u2f(ldg64(tgp + 16 + 2 * fy + q));
                    float2 gn = u2f(ldg64(tgp + 32 + 2 * fy + q));
                    float2 vr = u2f(acc[0 + q][p]);
                    float2 vz = u2f(acc[2 + q][p]);
                    float2 vn = u2f(acc[4 + q][p]);
#pragma unroll
                    for (int half = 0; half < 2; half++) {
                        int f = 4 * fy + 2 * q + half;
                        float ivr = half ? vr.y : vr.x;
                        float ivz = half ? vz.y : vz.x;
                        float ivn = half ? vn.y : vn.x;
                        float igr = half ? gr.y : gr.x;
                        float igz = half ? gz.y : gz.x;
                        float ign = half ? gn.y : gn.x;
                        float r = fast_sigmoid(igr + ivr);
                        float z = fast_sigmoid(igz + ivz);
                        float n = fast_tanh(ign + r * (ivn + sbhn[f]));
                        float hold = shf[f * PS + pp];
                        shf[f * PS + pp] = n + z * (hold - n);
                    }
                }
            }
        }
        __syncthreads();   // epilogue writes visible
    }

    // tail: 1 path per thread — write back (scattered on final step) + atomics
    int p = tid;
    if (p < pcount) {
        float v[32];
#pragma unroll
        for (int j = 0; j < 32; j++) v[j] = shf[j * PS + p];
        float4* dst;
        if (final_out) {
            int ord = g_order[s0 + p];
            dst = (float4*)(final_out + (size_t)ord * F_N);
        } else {
            dst = (float4*)(g_p + (size_t)(s0 + p) * F_N);
        }
#pragma unroll
        for (int q = 0; q < 8; q++)
            dst[q] = make_float4(v[4 * q], v[4 * q + 1], v[4 * q + 2], v[4 * q + 3]);
        int ln = slen[p];
#pragma unroll 1
        for (int t = 0; t <= ln; t++) {
            int ch = sidx[p * L_N + t];
            float* base = g_agg + (size_t)ch * F_N;
#pragma unroll
            for (int q = 0; q < 8; q++)
                red_add_v4(base + 4 * q, make_float4(v[4 * q], v[4 * q + 1],
                                                    v[4 * q + 2], v[4 * q + 3]));
        }
    }
}

// ---------------- fused layer2: c = GRU(agg, c); optionally gi1 table for next step ----------------
__global__ void __launch_bounds__(256) layer2_kernel(float* __restrict__ c,
                                                     const float* __restrict__ Wi2,
                                                     const float* __restrict__ Wh2,
                                                     const float* __restrict__ bi2,
                                                     const float* __restrict__ bh2,
                                                     const float* __restrict__ Wi1,
                                                     const float* __restrict__ bi1,
                                                     const float* __restrict__ bh1,
                                                     int want_table)
{
    __shared__ __align__(16) u64 swa[32 * 48];
    __shared__ __align__(16) u64 swh[32 * 48];
    __shared__ __align__(16) u64 sbuf[32 * PST];
    __shared__ float sbi[96];
    __shared__ float sbhn2[32];
    __shared__ float sb1[96];

    int tid = threadIdx.x;
    int s0 = blockIdx.x * L2TILE;
    int rcount = min(L2TILE, C_N - s0);

    for (int i = tid; i < 32 * 48; i += 256) {
        int k = i / 48, po = i % 48;
        swa[k * 48 + po] = f2u(Wi2[(2 * po) * 32 + k], Wi2[(2 * po + 1) * 32 + k]);
        swh[k * 48 + po] = f2u(Wh2[(2 * po) * 32 + k], Wh2[(2 * po + 1) * 32 + k]);
    }
    if (tid < 96) {
        sbi[tid] = bi2[tid] + (tid < 64 ? bh2[tid] : 0.0f);
        sb1[tid] = bi1[tid] + (tid < 64 ? bh1[tid] : 0.0f);
    }
    if (tid < 32) sbhn2[tid] = bh2[64 + tid];
    if (rcount < L2TILE) {
        for (int i = tid; i < 32 * L2TILE; i += 256) {
            int p = i & (L2TILE - 1);
            if (p >= rcount) sbuf[(i >> 6) * PST + p] = 0ull;
        }
    }
    for (int i = tid; i < rcount * 8; i += 256) {
        int p = i >> 3, kq = i & 7;
        float4 v = ((const float4*)(g_agg + (size_t)s0 * F_N))[i];
        sbuf[(4 * kq + 0) * PST + p] = f2u(v.x, v.x);
        sbuf[(4 * kq + 1) * PST + p] = f2u(v.y, v.y);
        sbuf[(4 * kq + 2) * PST + p] = f2u(v.z, v.z);
        sbuf[(4 * kq + 3) * PST + p] = f2u(v.w, v.w);
        ((float4*)(g_agg + (size_t)s0 * F_N))[i] = make_float4(0.f, 0.f, 0.f, 0.f);
    }
    __syncthreads();

    int px = tid >> 3, fy = tid & 7;
    int pbase = px * 2;

    u64 acc_i[6][2];
#pragma unroll
    for (int g = 0; g < 6; g++) { acc_i[g][0] = 0ull; acc_i[g][1] = 0ull; }
#pragma unroll 4
    for (int k = 0; k < 32; k++) {
        const ulonglong2* wrow = (const ulonglong2*)(swa + k * 48);
        ulonglong2 wr = wrow[fy];
        ulonglong2 wz = wrow[8 + fy];
        ulonglong2 wn = wrow[16 + fy];
        ulonglong2 h01 = *(const ulonglong2*)(sbuf + k * PST + pbase);
        u64 hp[2] = {h01.x, h01.y};
#pragma unroll
        for (int p = 0; p < 2; p++) {
            acc_i[0][p] = ffma2(hp[p], wr.x, acc_i[0][p]);
            acc_i[1][p] = ffma2(hp[p], wr.y, acc_i[1][p]);
            acc_i[2][p] = ffma2(hp[p], wz.x, acc_i[2][p]);
            acc_i[3][p] = ffma2(hp[p], wz.y, acc_i[3][p]);
            acc_i[4][p] = ffma2(hp[p], wn.x, acc_i[4][p]);
            acc_i[5][p] = ffma2(hp[p], wn.y, acc_i[5][p]);
        }
    }
    __syncthreads();

    for (int i = tid; i < rcount * 8; i += 256) {
        int p = i >> 3, kq = i & 7;
        float4 v = ((const float4*)(c + (size_t)s0 * F_N))[i];
        sbuf[(4 * kq + 0) * PST + p] = f2u(v.x, v.x);
        sbuf[(4 * kq + 1) * PST + p] = f2u(v.y, v.y);
        sbuf[(4 * kq + 2) * PST + p] = f2u(v.z, v.z);
        sbuf[(4 * kq + 3) * PST + p] = f2u(v.w, v.w);
    }
    if (want_table) {
        for (int i = tid; i < 32 * 48; i += 256) {
            int k = i / 48, po = i % 48;
            swa[k * 48 + po] = f2u(Wi1[(2 * po) * 32 + k], Wi1[(2 * po + 1) * 32 + k]);
        }
    }
    __syncthreads();

    u64 acc_h[6][2];
#pragma unroll
    for (int g = 0; g < 6; g++) { acc_h[g][0] = 0ull; acc_h[g][1] = 0ull; }
#pragma unroll 4
    for (int k = 0; k < 32; k++) {
        const ulonglong2* wrow = (const ulonglong2*)(swh + k * 48);
        ulonglong2 wr = wrow[fy];
        ulonglong2 wz = wrow[8 + fy];
        ulonglong2 wn = wrow[16 + fy];
        ulonglong2 h01 = *(const ulonglong2*)(sbuf + k * PST + pbase);
        u64 hp[2] = {h01.x, h01.y};
#pragma unroll
        for (int p = 0; p < 2; p++) {
            acc_h[0][p] = ffma2(hp[p], wr.x, acc_h[0][p]);
            acc_h[1][p] = ffma2(hp[p], wr.y, acc_h[1][p]);
            acc_h[2][p] = ffma2(hp[p], wz.x, acc_h[2][p]);
            acc_h[3][p] = ffma2(hp[p], wz.y, acc_h[3][p]);
            acc_h[4][p] = ffma2(hp[p], wn.x, acc_h[4][p]);
            acc_h[5][p] = ffma2(hp[p], wn.y, acc_h[5][p]);
        }
    }
    __syncthreads();

#pragma unroll
    for (int p = 0; p < 2; p++) {
        int pp = pbase + p;
        if (pp < rcount) {
            int ch = s0 + pp;
            u64* cdst = (u64*)(c + (size_t)ch * F_N);
#pragma unroll
            for (int q = 0; q < 2; q++) {
                float2 vi_r = u2f(acc_i[0 + q][p]);
                float2 vi_z = u2f(acc_i[2 + q][p]);
                float2 vi_n = u2f(acc_i[4 + q][p]);
                float2 vh_r = u2f(acc_h[0 + q][p]);
                float2 vh_z = u2f(acc_h[2 + q][p]);
                float2 vh_n = u2f(acc_h[4 + q][p]);
                float hnew2[2];
#pragma unroll
                for (int half = 0; half < 2; half++) {
                    int f = 4 * fy + 2 * q + half;
                    float ir = half ? vi_r.y : vi_r.x;
                    float iz = half ? vi_z.y : vi_z.x;
                    float in_ = half ? vi_n.y : vi_n.x;
                    float hr = half ? vh_r.y : vh_r.x;
                    float hz = half ? vh_z.y : vh_z.x;
                    float hn = half ? vh_n.y : vh_n.x;
                    float r = fast_sigmoid(ir + sbi[f] + hr);
                    float z = fast_sigmoid(iz + sbi[32 + f] + hz);
                    float n = fast_tanh(in_ + sbi[64 + f] + r * (hn + sbhn2[f]));
                    float hold = *((const float*)(sbuf + f * PST + pp));
                    float hv = n + z * (hold - n);
                    hnew2[half] = hv;
                    sbuf[f * PST + pp] = f2u(hv, hv);
                }
                cdst[2 * fy + q] = f2u(hnew2[0], hnew2[1]);
            }
        }
    }

    if (!want_table) return;
    __syncthreads();

    u64 acc[6][2];
#pragma unroll
    for (int g = 0; g < 6; g++) { acc[g][0] = 0ull; acc[g][1] = 0ull; }
#pragma unroll 4
    for (int k = 0; k < 32; k++) {
        const ulonglong2* wrow = (const ulonglong2*)(swa + k * 48);
        ulonglong2 wr = wrow[fy];
        ulonglong2 wz = wrow[8 + fy];
        ulonglong2 wn = wrow[16 + fy];
        ulonglong2 h01 = *(const ulonglong2*)(sbuf + k * PST + pbase);
        u64 hp[2] = {h01.x, h01.y};
#pragma unroll
        for (int p = 0; p < 2; p++) {
            acc[0][p] = ffma2(hp[p], wr.x, acc[0][p]);
            acc[1][p] = ffma2(hp[p], wr.y, acc[1][p]);
            acc[2][p] = ffma2(hp[p], wz.x, acc[2][p]);
            acc[3][p] = ffma2(hp[p], wz.y, acc[3][p]);
            acc[4][p] = ffma2(hp[p], wn.x, acc[4][p]);
            acc[5][p] = ffma2(hp[p], wn.y, acc[5][p]);
        }
    }
#pragma unroll
    for (int p = 0; p < 2; p++) {
        int pp = pbase + p;
        if (pp < rcount) {
            u64* trow = (u64*)(g_table + (size_t)(s0 + pp) * 96);
#pragma unroll
            for (int gate = 0; gate < 3; gate++) {
#pragma unroll
                for (int q = 0; q < 2; q++) {
                    int fb = 4 * fy + 2 * q;
                    float2 a = u2f(acc[2 * gate + q][p]);
                    trow[gate * 16 + 2 * fy + q] =
                        f2u(a.x + sb1[gate * 32 + fb], a.y + sb1[gate * 32 + fb + 1]);
                }
            }
        }
    }
}

// ---------------- launch ----------------
extern "C" void kernel_launch(void* const* d_in, const int* in_sizes, int n_in,
                              void* d_out, int out_size)
{
    const float* path_raw    = (const float*)d_in[0];
    const float* channel_raw = (const float*)d_in[1];
    const int*   pci         = (const int*)d_in[2];
    const int*   plen        = (const int*)d_in[3];
    // d_in[4] = num_steps (constant 5)
    const float* Wp  = (const float*)d_in[5];
    const float* bp  = (const float*)d_in[6];
    const float* Wc  = (const float*)d_in[7];
    const float* bc  = (const float*)d_in[8];
    const float* Wi1 = (const float*)d_in[9];
    const float* Wh1 = (const float*)d_in[10];
    const float* bi1 = (const float*)d_in[11];
    const float* bh1 = (const float*)d_in[12];
    const float* Wi2 = (const float*)d_in[13];
    const float* Wh2 = (const float*)d_in[14];
    const float* bi2 = (const float*)d_in[15];
    const float* bh2 = (const float*)d_in[16];

    float* outp = (float*)d_out;
    float* c    = outp + (size_t)P_N * F_N;

    int gridScan = (P_N + STILE - 1) / STILE;     // 782
    int gridL2   = (C_N + L2TILE - 1) / L2TILE;   // 782

    hist_prefix_kernel<<<PB_BLOCKS, 256>>>(plen);
    scatter_kernel<<<PB_BLOCKS, 256>>>(plen);
    buildinit_gi_kernel<<<PB_BLOCKS + CB_BLOCKS, 256>>>(plen, pci, path_raw, channel_raw,
                                                        Wp, bp, Wc, bc, Wi1, bi1, bh1, c);
    for (int st = 0; st < NSTEPS; st++) {
        scan4_kernel<<<gridScan, 256>>>(Wh1, bh1, (st == NSTEPS - 1) ? outp : nullptr);
        layer2_kernel<<<gridL2, 256>>>(c, Wi2, Wh2, bi2, bh2, Wi1, bi1, bh1,
                                       (st < NSTEPS - 1) ? 1 : 0);
    }
}

// round 8
// speedup vs baseline: 1.4091x; 1.2213x over previous
#include <cuda_runtime.h>

#define P_N 200000
#define C_N 50000
#define L_N 8
#define F_N 32
#define DIN 64
#define NSTEPS 5

#define PB_BLOCKS ((P_N + 255) / 256)   // 782
#define CB_BLOCKS ((C_N + 255) / 256)   // 196

#define STILE 128                       // scan paths per block
#define PS 132                          // float stride, mult of 4, mod 32 = 4
#define L2TILE 64
#define PS2 68                          // float stride for layer2 staging

typedef unsigned long long u64;

// ---------------- device scratch ----------------
__device__ float g_p[(size_t)P_N * F_N];
__device__ int   g_order[P_N];
__device__ int   g_idx[(size_t)P_N * L_N];
__device__ int   g_len[P_N];
__device__ float g_agg[(size_t)C_N * F_N];
__device__ float g_table[(size_t)C_N * 96];
__device__ int   g_cnt[16];
__device__ int   g_blkhist[PB_BLOCKS * 8];
__device__ int   g_done;

// ---------------- helpers ----------------
__device__ __forceinline__ u64 ffma2(u64 a, u64 b, u64 c) {
    u64 d;
    asm("fma.rn.f32x2 %0, %1, %2, %3;" : "=l"(d) : "l"(a), "l"(b), "l"(c));
    return d;
}
__device__ __forceinline__ float2 u2f(u64 v) {
    float2 r;
    asm("mov.b64 {%0,%1}, %2;" : "=f"(r.x), "=f"(r.y) : "l"(v));
    return r;
}
__device__ __forceinline__ u64 f2u(float a, float b) {
    u64 r;
    asm("mov.b64 %0, {%1,%2};" : "=l"(r) : "f"(a), "f"(b));
    return r;
}
__device__ __forceinline__ float hsum(u64 v) { float2 f = u2f(v); return f.x + f.y; }

__device__ __forceinline__ float tanh_ap(float x) {
    float y;
    asm("tanh.approx.f32 %0, %1;" : "=f"(y) : "f"(x));
    return y;
}
__device__ __forceinline__ float fast_sigmoid(float v) {
    return fmaf(0.5f, tanh_ap(0.5f * v), 0.5f);
}
__device__ __forceinline__ float fast_tanh(float v) { return tanh_ap(v); }

__device__ __forceinline__ void red_add_v4(float* p, float4 v) {
    asm volatile("red.global.add.v4.f32 [%0], {%1,%2,%3,%4};"
                 :: "l"(p), "f"(v.x), "f"(v.y), "f"(v.z), "f"(v.w) : "memory");
}
__device__ __forceinline__ u64 ldg64(const u64* p) {
    u64 v;
    asm("ld.global.nc.b64 %0, [%1];" : "=l"(v) : "l"(p));
    return v;
}

// ---------------- fused hist + prefix (last-block-done) ----------------
__global__ void __launch_bounds__(256) hist_prefix_kernel(const int* __restrict__ plen) {
    __shared__ int lh[8];
    __shared__ int slast;
    int tid = threadIdx.x;
    if (tid < 8) lh[tid] = 0;
    __syncthreads();
    int i = blockIdx.x * 256 + tid;
    if (i < P_N) {
        int b = plen[i]; b = b < 0 ? 0 : (b > 7 ? 7 : b);
        atomicAdd(&lh[b], 1);
    }
    __syncthreads();
    if (tid < 8) g_blkhist[blockIdx.x * 8 + tid] = lh[tid];
    __threadfence();
    if (tid == 0) {
        int t = atomicAdd(&g_done, 1);
        slast = (t == gridDim.x - 1) ? 1 : 0;
    }
    __syncthreads();
    if (slast) {
        __threadfence();
        int local[8] = {0, 0, 0, 0, 0, 0, 0, 0};
        for (int j = tid; j < PB_BLOCKS; j += 256) {
#pragma unroll
            for (int b = 0; b < 8; b++) local[b] += g_blkhist[j * 8 + b];
        }
        if (tid < 8) lh[tid] = 0;
        __syncthreads();
#pragma unroll
        for (int b = 0; b < 8; b++) atomicAdd(&lh[b], local[b]);
        __syncthreads();
        if (tid == 0) {
            int acc = 0;
#pragma unroll
            for (int b = 7; b >= 0; b--) { int cv = lh[b]; g_cnt[b] = acc; acc += cv; }
            g_done = 0;
        }
    }
}

__global__ void __launch_bounds__(256) scatter_kernel(const int* __restrict__ plen) {
    int i = blockIdx.x * 256 + threadIdx.x;
    if (i < P_N) {
        int b = plen[i]; b = b < 0 ? 0 : (b > 7 ? 7 : b);
        int pos = atomicAdd(&g_cnt[b], 1);
        g_order[pos] = i;
    }
}

// ---------------- fused build(paths) + initc + step0 gi1 table (channels) ----------------
__global__ void __launch_bounds__(256) buildinit_gi_kernel(const int* __restrict__ plen,
                                                           const int* __restrict__ pci,
                                                           const float* __restrict__ praw,
                                                           const float* __restrict__ craw,
                                                           const float* __restrict__ Wp,
                                                           const float* __restrict__ bp,
                                                           const float* __restrict__ Wc,
                                                           const float* __restrict__ bc,
                                                           const float* __restrict__ Wi1,
                                                           const float* __restrict__ bi1,
                                                           const float* __restrict__ bh1,
                                                           float* __restrict__ c)
{
    __shared__ __align__(16) float sWt[F_N * DIN];
    __shared__ float sb[F_N];
    __shared__ __align__(16) float sWi1f[96 * 32];
    __shared__ float sb1[96];
    int tid = threadIdx.x;
    bool isPath = blockIdx.x < PB_BLOCKS;
    const float* W = isPath ? Wp : Wc;
    const float* b = isPath ? bp : bc;
    for (int i = tid; i < DIN * F_N; i += 256) {
        int d = i >> 5, f = i & 31;
        sWt[f * DIN + d] = W[i];
    }
    if (tid < F_N) sb[tid] = b[tid];
    if (!isPath) {
        for (int i = tid; i < 96 * 32; i += 256) sWi1f[i] = Wi1[i];
        if (tid < 96) sb1[tid] = bi1[tid] + (tid < 64 ? bh1[tid] : 0.0f);
    }
    __syncthreads();

    int row, srcrow;
    const float* xsrc;
    float* dst;
    if (isPath) {
        row = blockIdx.x * 256 + tid;
        if (row >= P_N) return;
        srcrow = g_order[row];
        g_len[row] = plen[srcrow];
        const int4* si = (const int4*)(pci + (size_t)srcrow * L_N);
        int4* di = (int4*)(g_idx + (size_t)row * L_N);
        di[0] = si[0]; di[1] = si[1];
        xsrc = praw;
        dst = g_p + (size_t)row * F_N;
    } else {
        row = (blockIdx.x - PB_BLOCKS) * 256 + tid;
        if (row >= C_N) return;
        srcrow = row;
        xsrc = craw;
        dst = c + (size_t)row * F_N;
    }

    u64 x2[32];
    const ulonglong2* xg = (const ulonglong2*)(xsrc + (size_t)srcrow * DIN);
#pragma unroll
    for (int q = 0; q < 16; q++) { ulonglong2 v = xg[q]; x2[2 * q] = v.x; x2[2 * q + 1] = v.y; }
    const u64* wt = (const u64*)sWt;
    float cr[32];
    for (int f0 = 0; f0 < F_N; f0 += 4) {
        u64 a0 = 0, a1 = 0, a2 = 0, a3 = 0;
        const u64* w0 = wt + (f0 + 0) * 32;
        const u64* w1 = wt + (f0 + 1) * 32;
        const u64* w2 = wt + (f0 + 2) * 32;
        const u64* w3 = wt + (f0 + 3) * 32;
#pragma unroll
        for (int k = 0; k < 32; k++) {
            a0 = ffma2(x2[k], w0[k], a0);
            a1 = ffma2(x2[k], w1[k], a1);
            a2 = ffma2(x2[k], w2[k], a2);
            a3 = ffma2(x2[k], w3[k], a3);
        }
        cr[f0 + 0] = fmaxf(hsum(a0) + sb[f0 + 0], 0.0f);
        cr[f0 + 1] = fmaxf(hsum(a1) + sb[f0 + 1], 0.0f);
        cr[f0 + 2] = fmaxf(hsum(a2) + sb[f0 + 2], 0.0f);
        cr[f0 + 3] = fmaxf(hsum(a3) + sb[f0 + 3], 0.0f);
    }
    float4* out4 = (float4*)dst;
#pragma unroll
    for (int q = 0; q < 8; q++)
        out4[q] = make_float4(cr[4 * q], cr[4 * q + 1], cr[4 * q + 2], cr[4 * q + 3]);

    if (!isPath) {
        float4 z4 = make_float4(0.f, 0.f, 0.f, 0.f);
        float4* ag = (float4*)(g_agg + (size_t)row * F_N);
#pragma unroll
        for (int q = 0; q < 8; q++) ag[q] = z4;
        u64 xc[16];
#pragma unroll
        for (int k = 0; k < 16; k++) xc[k] = f2u(cr[2 * k], cr[2 * k + 1]);
        u64* trow = (u64*)(g_table + (size_t)row * 96);
        for (int f0 = 0; f0 < 96; f0 += 2) {
            const u64* wr0 = (const u64*)(sWi1f + (f0 + 0) * 32);
            const u64* wr1 = (const u64*)(sWi1f + (f0 + 1) * 32);
            u64 a0 = 0, a1 = 0;
#pragma unroll
            for (int k = 0; k < 16; k++) {
                a0 = ffma2(xc[k], wr0[k], a0);
                a1 = ffma2(xc[k], wr1[k], a1);
            }
            int gate = f0 >> 5, fin = f0 & 31;
            trow[gate * 16 + (fin >> 1)] = f2u(hsum(a0) + sb1[f0], hsum(a1) + sb1[f0 + 1]);
        }
    }
}

// ---------------- scan5: 128 paths/block, 256 thr = 16(px) x 16(fy), tile 8p x 6o ----------------
// acc = 3 gates x 1 u64 x 8 paths = 24 u64 (48 regs) -> 2 blocks/SM.
// Per k per thread: 3 LDS.64 (w broadcast) + 2 LDS.128 (h) -> 24 FFMA2.
__global__ void __launch_bounds__(256, 2) scan5_kernel(const float* __restrict__ Wh,
                                                       const float* __restrict__ bh,
                                                       float* __restrict__ final_out)
{
    __shared__ __align__(16) u64   sww[32 * 48];     // [k][out-pair]: r 0..15, z 16..31, n 32..47
    __shared__ __align__(16) float shf[32 * PS];     // [k][path]
    __shared__ int sidx[STILE * L_N];
    __shared__ short slen[STILE];
    __shared__ float sbhn[32];

    int tid = threadIdx.x;
    int s0 = blockIdx.x * STILE;
    int pcount = min(STILE, P_N - s0);

    for (int i = tid; i < 32 * 48; i += 256) {
        int k = i / 48, po = i % 48;
        sww[k * 48 + po] = f2u(Wh[(2 * po) * 32 + k], Wh[(2 * po + 1) * 32 + k]);
    }
    if (tid < 32) sbhn[tid] = bh[64 + tid];
    for (int i = tid; i < pcount * 2; i += 256)
        ((int4*)sidx)[i] = ((const int4*)(g_idx + (size_t)s0 * L_N))[i];
    // padding paths: valid dummy channel 0 (loads are unconditional; stores guarded)
    for (int i = pcount * 8 + tid; i < STILE * L_N; i += 256) sidx[i] = 0;
    if (tid < STILE) slen[tid] = (tid < pcount) ? (short)g_len[s0 + tid] : (short)-1;
    if (pcount < STILE) {
        for (int i = tid; i < 32 * STILE; i += 256) {
            int p = i & (STILE - 1);
            if (p >= pcount) shf[(i >> 7) * PS + p] = 0.0f;
        }
    }
    for (int i = tid; i < pcount * 8; i += 256) {
        int p = i >> 3, kq = i & 7;
        float4 v = ((const float4*)(g_p + (size_t)s0 * F_N))[i];
        shf[(4 * kq + 0) * PS + p] = v.x;
        shf[(4 * kq + 1) * PS + p] = v.y;
        shf[(4 * kq + 2) * PS + p] = v.z;
        shf[(4 * kq + 3) * PS + p] = v.w;
    }
    __syncthreads();

    int tmax = slen[0];                 // descending sort => block max
    int px = tid >> 4;                  // 0..15
    int fy = tid & 15;                  // 0..15
    int pbase = px * 8;

    for (int t = 0; t <= tmax; t++) {
        u64 ar[8], az[8], an[8];
#pragma unroll
        for (int p = 0; p < 8; p++) { ar[p] = 0ull; az[p] = 0ull; an[p] = 0ull; }

#pragma unroll 4
        for (int k = 0; k < 32; k++) {
            const u64* wrow = sww + k * 48;
            u64 wr = wrow[fy];
            u64 wz = wrow[16 + fy];
            u64 wn = wrow[32 + fy];
            const float4* hr = (const float4*)(shf + k * PS + pbase);
            float4 ha = hr[0];
            float4 hb = hr[1];
            u64 hd[8];
            hd[0] = f2u(ha.x, ha.x); hd[1] = f2u(ha.y, ha.y);
            hd[2] = f2u(ha.z, ha.z); hd[3] = f2u(ha.w, ha.w);
            hd[4] = f2u(hb.x, hb.x); hd[5] = f2u(hb.y, hb.y);
            hd[6] = f2u(hb.z, hb.z); hd[7] = f2u(hb.w, hb.w);
#pragma unroll
            for (int p = 0; p < 8; p++) {
                ar[p] = ffma2(hd[p], wr, ar[p]);
                az[p] = ffma2(hd[p], wz, az[p]);
                an[p] = ffma2(hd[p], wn, an[p]);
            }
        }
        __syncthreads();   // k-loop reads of shf complete

        // epilogue: f = 2fy, 2fy+1; paths pbase..pbase+7.
        // Table loads unconditional (sidx always a valid channel); store guarded.
#pragma unroll
        for (int p = 0; p < 8; p++) {
            int pp = pbase + p;
            int ch = sidx[pp * L_N + t];
            const u64* tgp = (const u64*)(g_table + (size_t)ch * 96);
            u64 lgr = ldg64(tgp + fy);
            u64 lgz = ldg64(tgp + 16 + fy);
            u64 lgn = ldg64(tgp + 32 + fy);
            bool active = (t <= slen[pp]);
            float2 gr = u2f(lgr), gz = u2f(lgz), gn = u2f(lgn);
            float2 vr = u2f(ar[p]), vz = u2f(az[p]), vn = u2f(an[p]);
#pragma unroll
            for (int half = 0; half < 2; half++) {
                int f = 2 * fy + half;
                float ivr = half ? vr.y : vr.x;
                float ivz = half ? vz.y : vz.x;
                float ivn = half ? vn.y : vn.x;
                float igr = half ? gr.y : gr.x;
                float igz = half ? gz.y : gz.x;
                float ign = half ? gn.y : gn.x;
                float r = fast_sigmoid(igr + ivr);
                float z = fast_sigmoid(igz + ivz);
                float n = fast_tanh(ign + r * (ivn + sbhn[f]));
                float hold = shf[f * PS + pp];
                if (active) shf[f * PS + pp] = n + z * (hold - n);
            }
        }
        __syncthreads();   // epilogue writes visible
    }

    // tail: 2 threads per path (kc = feature half) — write back + atomics
    int p = tid & (STILE - 1);
    int kc = tid >> 7;
    if (p < pcount) {
        float v[16];
#pragma unroll
        for (int j = 0; j < 16; j++) v[j] = shf[(kc * 16 + j) * PS + p];
        float4* dst;
        if (final_out) {
            int ord = g_order[s0 + p];
            dst = (float4*)(final_out + (size_t)ord * F_N + kc * 16);
        } else {
            dst = (float4*)(g_p + (size_t)(s0 + p) * F_N + kc * 16);
        }
#pragma unroll
        for (int q = 0; q < 4; q++)
            dst[q] = make_float4(v[4 * q], v[4 * q + 1], v[4 * q + 2], v[4 * q + 3]);
        int ln = slen[p];
#pragma unroll 1
        for (int t = 0; t <= ln; t++) {
            int ch = sidx[p * L_N + t];
            float* base = g_agg + (size_t)ch * F_N + kc * 16;
            red_add_v4(base + 0,  make_float4(v[0],  v[1],  v[2],  v[3]));
            red_add_v4(base + 4,  make_float4(v[4],  v[5],  v[6],  v[7]));
            red_add_v4(base + 8,  make_float4(v[8],  v[9],  v[10], v[11]));
            red_add_v4(base + 12, make_float4(v[12], v[13], v[14], v[15]));
        }
    }
}

// ---------------- fused layer2: c = GRU(agg, c); optionally gi1 table ----------------
// 64 rows/block, 256 thr = 16(px) x 16(fy), tile 4p x 6o.
__global__ void __launch_bounds__(256) layer2_kernel(float* __restrict__ c,
                                                     const float* __restrict__ Wi2,
                                                     const float* __restrict__ Wh2,
                                                     const float* __restrict__ bi2,
                                                     const float* __restrict__ bh2,
                                                     const float* __restrict__ Wi1,
                                                     const float* __restrict__ bi1,
                                                     const float* __restrict__ bh1,
                                                     int want_table)
{
    __shared__ __align__(16) u64   swa[32 * 48];     // Wi2 pairs, later Wi1 pairs
    __shared__ __align__(16) u64   swh[32 * 48];     // Wh2 pairs
    __shared__ __align__(16) float sbuf[32 * PS2];   // staging [k][row]: agg -> c -> cnew
    __shared__ float sbi[96];
    __shared__ float sbhn2[32];
    __shared__ float sb1[96];

    int tid = threadIdx.x;
    int s0 = blockIdx.x * L2TILE;
    int rcount = min(L2TILE, C_N - s0);

    for (int i = tid; i < 32 * 48; i += 256) {
        int k = i / 48, po = i % 48;
        swa[k * 48 + po] = f2u(Wi2[(2 * po) * 32 + k], Wi2[(2 * po + 1) * 32 + k]);
        swh[k * 48 + po] = f2u(Wh2[(2 * po) * 32 + k], Wh2[(2 * po + 1) * 32 + k]);
    }
    if (tid < 96) {
        sbi[tid] = bi2[tid] + (tid < 64 ? bh2[tid] : 0.0f);
        sb1[tid] = bi1[tid] + (tid < 64 ? bh1[tid] : 0.0f);
    }
    if (tid < 32) sbhn2[tid] = bh2[64 + tid];
    if (rcount < L2TILE) {
        for (int i = tid; i < 32 * L2TILE; i += 256) {
            int p = i & (L2TILE - 1);
            if (p >= rcount) sbuf[(i >> 6) * PS2 + p] = 0.0f;
        }
    }
    for (int i = tid; i < rcount * 8; i += 256) {
        int p = i >> 3, kq = i & 7;
        float4 v = ((const float4*)(g_agg + (size_t)s0 * F_N))[i];
        sbuf[(4 * kq + 0) * PS2 + p] = v.x;
        sbuf[(4 * kq + 1) * PS2 + p] = v.y;
        sbuf[(4 * kq + 2) * PS2 + p] = v.z;
        sbuf[(4 * kq + 3) * PS2 + p] = v.w;
        ((float4*)(g_agg + (size_t)s0 * F_N))[i] = make_float4(0.f, 0.f, 0.f, 0.f);
    }
    __syncthreads();

    int px = tid >> 4, fy = tid & 15;
    int pbase = px * 4;

    u64 ir[4], iz[4], in_[4];
#pragma unroll
    for (int p = 0; p < 4; p++) { ir[p] = 0ull; iz[p] = 0ull; in_[p] = 0ull; }
#pragma unroll 4
    for (int k = 0; k < 32; k++) {
        const u64* wrow = swa + k * 48;
        u64 wr = wrow[fy];
        u64 wz = wrow[16 + fy];
        u64 wn = wrow[32 + fy];
        float4 ha = *(const float4*)(sbuf + k * PS2 + pbase);
        u64 hd[4];
        hd[0] = f2u(ha.x, ha.x); hd[1] = f2u(ha.y, ha.y);
        hd[2] = f2u(ha.z, ha.z); hd[3] = f2u(ha.w, ha.w);
#pragma unroll
        for (int p = 0; p < 4; p++) {
            ir[p]  = ffma2(hd[p], wr, ir[p]);
            iz[p]  = ffma2(hd[p], wz, iz[p]);
            in_[p] = ffma2(hd[p], wn, in_[p]);
        }
    }
    __syncthreads();

    // restage: sbuf <- c rows; swa <- Wi1 pairs for table phase
    for (int i = tid; i < rcount * 8; i += 256) {
        int p = i >> 3, kq = i & 7;
        float4 v = ((const float4*)(c + (size_t)s0 * F_N))[i];
        sbuf[(4 * kq + 0) * PS2 + p] = v.x;
        sbuf[(4 * kq + 1) * PS2 + p] = v.y;
        sbuf[(4 * kq + 2) * PS2 + p] = v.z;
        sbuf[(4 * kq + 3) * PS2 + p] = v.w;
    }
    if (want_table) {
        for (int i = tid; i < 32 * 48; i += 256) {
            int k = i / 48, po = i % 48;
            swa[k * 48 + po] = f2u(Wi1[(2 * po) * 32 + k], Wi1[(2 * po + 1) * 32 + k]);
        }
    }
    __syncthreads();

    u64 hr_[4], hz_[4], hn_[4];
#pragma unroll
    for (int p = 0; p < 4; p++) { hr_[p] = 0ull; hz_[p] = 0ull; hn_[p] = 0ull; }
#pragma unroll 4
    for (int k = 0; k < 32; k++) {
        const u64* wrow = swh + k * 48;
        u64 wr = wrow[fy];
        u64 wz = wrow[16 + fy];
        u64 wn = wrow[32 + fy];
        float4 ha = *(const float4*)(sbuf + k * PS2 + pbase);
        u64 hd[4];
        hd[0] = f2u(ha.x, ha.x); hd[1] = f2u(ha.y, ha.y);
        hd[2] = f2u(ha.z, ha.z); hd[3] = f2u(ha.w, ha.w);
#pragma unroll
        for (int p = 0; p < 4; p++) {
            hr_[p] = ffma2(hd[p], wr, hr_[p]);
            hz_[p] = ffma2(hd[p], wz, hz_[p]);
            hn_[p] = ffma2(hd[p], wn, hn_[p]);
        }
    }
    __syncthreads();   // k-loop reads done before in-place cnew writes

#pragma unroll
    for (int p = 0; p < 4; p++) {
        int pp = pbase + p;
        if (pp < rcount) {
            int ch = s0 + pp;
            u64* cdst = (u64*)(c + (size_t)ch * F_N);
            float2 vi_r = u2f(ir[p]),  vi_z = u2f(iz[p]),  vi_n = u2f(in_[p]);
            float2 vh_r = u2f(hr_[p]), vh_z = u2f(hz_[p]), vh_n = u2f(hn_[p]);
            float hnew2[2];
#pragma unroll
            for (int half = 0; half < 2; half++) {
                int f = 2 * fy + half;
                float a_ir = half ? vi_r.y : vi_r.x;
                float a_iz = half ? vi_z.y : vi_z.x;
                float a_in = half ? vi_n.y : vi_n.x;
                float a_hr = half ? vh_r.y : vh_r.x;
                float a_hz = half ? vh_z.y : vh_z.x;
                float a_hn = half ? vh_n.y : vh_n.x;
                float r = fast_sigmoid(a_ir + sbi[f] + a_hr);
                float z = fast_sigmoid(a_iz + sbi[32 + f] + a_hz);
                float n = fast_tanh(a_in + sbi[64 + f] + r * (a_hn + sbhn2[f]));
                float hold = sbuf[f * PS2 + pp];
                float hv = n + z * (hold - n);
                hnew2[half] = hv;
                sbuf[f * PS2 + pp] = hv;
            }
            cdst[fy] = f2u(hnew2[0], hnew2[1]);
        }
    }

    if (!want_table) return;
    __syncthreads();   // cnew staged

    u64 tr[4], tz[4], tn[4];
#pragma unroll
    for (int p = 0; p < 4; p++) { tr[p] = 0ull; tz[p] = 0ull; tn[p] = 0ull; }
#pragma unroll 4
    for (int k = 0; k < 32; k++) {
        const u64* wrow = swa + k * 48;
        u64 wr = wrow[fy];
        u64 wz = wrow[16 + fy];
        u64 wn = wrow[32 + fy];
        float4 ha = *(const float4*)(sbuf + k * PS2 + pbase);
        u64 hd[4];
        hd[0] = f2u(ha.x, ha.x); hd[1] = f2u(ha.y, ha.y);
        hd[2] = f2u(ha.z, ha.z); hd[3] = f2u(ha.w, ha.w);
#pragma unroll
        for (int p = 0; p < 4; p++) {
            tr[p] = ffma2(hd[p], wr, tr[p]);
            tz[p] = ffma2(hd[p], wz, tz[p]);
            tn[p] = ffma2(hd[p], wn, tn[p]);
        }
    }
#pragma unroll
    for (int p = 0; p < 4; p++) {
        int pp = pbase + p;
        if (pp < rcount) {
            u64* trow = (u64*)(g_table + (size_t)(s0 + pp) * 96);
            float2 a0 = u2f(tr[p]), a1 = u2f(tz[p]), a2 = u2f(tn[p]);
            trow[fy]      = f2u(a0.x + sb1[2 * fy],      a0.y + sb1[2 * fy + 1]);
            trow[16 + fy] = f2u(a1.x + sb1[32 + 2 * fy], a1.y + sb1[32 + 2 * fy + 1]);
            trow[32 + fy] = f2u(a2.x + sb1[64 + 2 * fy], a2.y + sb1[64 + 2 * fy + 1]);
        }
    }
}

// ---------------- launch ----------------
extern "C" void kernel_launch(void* const* d_in, const int* in_sizes, int n_in,
                              void* d_out, int out_size)
{
    const float* path_raw    = (const float*)d_in[0];
    const float* channel_raw = (const float*)d_in[1];
    const int*   pci         = (const int*)d_in[2];
    const int*   plen        = (const int*)d_in[3];
    // d_in[4] = num_steps (constant 5)
    const float* Wp  = (const float*)d_in[5];
    const float* bp  = (const float*)d_in[6];
    const float* Wc  = (const float*)d_in[7];
    const float* bc  = (const float*)d_in[8];
    const float* Wi1 = (const float*)d_in[9];
    const float* Wh1 = (const float*)d_in[10];
    const float* bi1 = (const float*)d_in[11];
    const float* bh1 = (const float*)d_in[12];
    const float* Wi2 = (const float*)d_in[13];
    const float* Wh2 = (const float*)d_in[14];
    const float* bi2 = (const float*)d_in[15];
    const float* bh2 = (const float*)d_in[16];

    float* outp = (float*)d_out;
    float* c    = outp + (size_t)P_N * F_N;

    int gridScan = (P_N + STILE - 1) / STILE;     // 1563
    int gridL2   = (C_N + L2TILE - 1) / L2TILE;   // 782

    hist_prefix_kernel<<<PB_BLOCKS, 256>>>(plen);
    scatter_kernel<<<PB_BLOCKS, 256>>>(plen);
    buildinit_gi_kernel<<<PB_BLOCKS + CB_BLOCKS, 256>>>(plen, pci, path_raw, channel_raw,
                                                        Wp, bp, Wc, bc, Wi1, bi1, bh1, c);
    for (int st = 0; st < NSTEPS; st++) {
        scan5_kernel<<<gridScan, 256>>>(Wh1, bh1, (st == NSTEPS - 1) ? outp : nullptr);
        layer2_kernel<<<gridL2, 256>>>(c, Wi2, Wh2, bi2, bh2, Wi1, bi1, bh1,
                                       (st < NSTEPS - 1) ? 1 : 0);
    }
}

// round 9
// speedup vs baseline: 1.5717x; 1.1154x over previous
#include <cuda_runtime.h>

#define P_N 200000
#define C_N 50000
#define L_N 8
#define F_N 32
#define DIN 64
#define NSTEPS 5

#define PB_BLOCKS ((P_N + 255) / 256)   // 782
#define CB_BLOCKS ((C_N + 255) / 256)   // 196

#define STILE 128                       // scan paths per block
#define PS 128                          // float stride of shf rows (swizzled cols)
#define L2TILE 64
#define PS2 68                          // float stride for layer2 staging

typedef unsigned long long u64;

// ---------------- device scratch ----------------
__device__ float g_p[(size_t)P_N * F_N];
__device__ int   g_order[P_N];
__device__ int   g_idx[(size_t)P_N * L_N];
__device__ int   g_len[P_N];
__device__ float g_agg[(size_t)C_N * F_N];
__device__ float g_table[(size_t)C_N * 96];
__device__ int   g_cnt[16];
__device__ int   g_blkhist[PB_BLOCKS * 8];
__device__ int   g_done;

// ---------------- helpers ----------------
__device__ __forceinline__ u64 ffma2(u64 a, u64 b, u64 c) {
    u64 d;
    asm("fma.rn.f32x2 %0, %1, %2, %3;" : "=l"(d) : "l"(a), "l"(b), "l"(c));
    return d;
}
__device__ __forceinline__ float2 u2f(u64 v) {
    float2 r;
    asm("mov.b64 {%0,%1}, %2;" : "=f"(r.x), "=f"(r.y) : "l"(v));
    return r;
}
__device__ __forceinline__ u64 f2u(float a, float b) {
    u64 r;
    asm("mov.b64 %0, {%1,%2};" : "=l"(r) : "f"(a), "f"(b));
    return r;
}
__device__ __forceinline__ float hsum(u64 v) { float2 f = u2f(v); return f.x + f.y; }

__device__ __forceinline__ float tanh_ap(float x) {
    float y;
    asm("tanh.approx.f32 %0, %1;" : "=f"(y) : "f"(x));
    return y;
}
__device__ __forceinline__ float fast_sigmoid(float v) {
    return fmaf(0.5f, tanh_ap(0.5f * v), 0.5f);
}
__device__ __forceinline__ float fast_tanh(float v) { return tanh_ap(v); }

__device__ __forceinline__ void red_add_v4(float* p, float4 v) {
    asm volatile("red.global.add.v4.f32 [%0], {%1,%2,%3,%4};"
                 :: "l"(p), "f"(v.x), "f"(v.y), "f"(v.z), "f"(v.w) : "memory");
}
__device__ __forceinline__ u64 ldg64(const u64* p) {
    u64 v;
    asm("ld.global.nc.b64 %0, [%1];" : "=l"(v) : "l"(p));
    return v;
}

// ---------------- fused hist + prefix (last-block-done) ----------------
__global__ void __launch_bounds__(256) hist_prefix_kernel(const int* __restrict__ plen) {
    __shared__ int lh[8];
    __shared__ int slast;
    int tid = threadIdx.x;
    if (tid < 8) lh[tid] = 0;
    __syncthreads();
    int i = blockIdx.x * 256 + tid;
    if (i < P_N) {
        int b = plen[i]; b = b < 0 ? 0 : (b > 7 ? 7 : b);
        atomicAdd(&lh[b], 1);
    }
    __syncthreads();
    if (tid < 8) g_blkhist[blockIdx.x * 8 + tid] = lh[tid];
    __threadfence();
    if (tid == 0) {
        int t = atomicAdd(&g_done, 1);
        slast = (t == gridDim.x - 1) ? 1 : 0;
    }
    __syncthreads();
    if (slast) {
        __threadfence();
        int local[8] = {0, 0, 0, 0, 0, 0, 0, 0};
        for (int j = tid; j < PB_BLOCKS; j += 256) {
#pragma unroll
            for (int b = 0; b < 8; b++) local[b] += g_blkhist[j * 8 + b];
        }
        if (tid < 8) lh[tid] = 0;
        __syncthreads();
#pragma unroll
        for (int b = 0; b < 8; b++) atomicAdd(&lh[b], local[b]);
        __syncthreads();
        if (tid == 0) {
            int acc = 0;
#pragma unroll
            for (int b = 7; b >= 0; b--) { int cv = lh[b]; g_cnt[b] = acc; acc += cv; }
            g_done = 0;
        }
    }
}

__global__ void __launch_bounds__(256) scatter_kernel(const int* __restrict__ plen) {
    int i = blockIdx.x * 256 + threadIdx.x;
    if (i < P_N) {
        int b = plen[i]; b = b < 0 ? 0 : (b > 7 ? 7 : b);
        int pos = atomicAdd(&g_cnt[b], 1);
        g_order[pos] = i;
    }
}

// ---------------- fused build(paths) + initc + step0 gi1 table (channels) ----------------
__global__ void __launch_bounds__(256) buildinit_gi_kernel(const int* __restrict__ plen,
                                                           const int* __restrict__ pci,
                                                           const float* __restrict__ praw,
                                                           const float* __restrict__ craw,
                                                           const float* __restrict__ Wp,
                                                           const float* __restrict__ bp,
                                                           const float* __restrict__ Wc,
                                                           const float* __restrict__ bc,
                                                           const float* __restrict__ Wi1,
                                                           const float* __restrict__ bi1,
                                                           const float* __restrict__ bh1,
                                                           float* __restrict__ c)
{
    __shared__ __align__(16) float sWt[F_N * DIN];
    __shared__ float sb[F_N];
    __shared__ __align__(16) float sWi1f[96 * 32];
    __shared__ float sb1[96];
    int tid = threadIdx.x;
    bool isPath = blockIdx.x < PB_BLOCKS;
    const float* W = isPath ? Wp : Wc;
    const float* b = isPath ? bp : bc;
    for (int i = tid; i < DIN * F_N; i += 256) {
        int d = i >> 5, f = i & 31;
        sWt[f * DIN + d] = W[i];
    }
    if (tid < F_N) sb[tid] = b[tid];
    if (!isPath) {
        for (int i = tid; i < 96 * 32; i += 256) sWi1f[i] = Wi1[i];
        if (tid < 96) sb1[tid] = bi1[tid] + (tid < 64 ? bh1[tid] : 0.0f);
    }
    __syncthreads();

    int row, srcrow;
    const float* xsrc;
    float* dst;
    if (isPath) {
        row = blockIdx.x * 256 + tid;
        if (row >= P_N) return;
        srcrow = g_order[row];
        g_len[row] = plen[srcrow];
        const int4* si = (const int4*)(pci + (size_t)srcrow * L_N);
        int4* di = (int4*)(g_idx + (size_t)row * L_N);
        di[0] = si[0]; di[1] = si[1];
        xsrc = praw;
        dst = g_p + (size_t)row * F_N;
    } else {
        row = (blockIdx.x - PB_BLOCKS) * 256 + tid;
        if (row >= C_N) return;
        srcrow = row;
        xsrc = craw;
        dst = c + (size_t)row * F_N;
    }

    u64 x2[32];
    const ulonglong2* xg = (const ulonglong2*)(xsrc + (size_t)srcrow * DIN);
#pragma unroll
    for (int q = 0; q < 16; q++) { ulonglong2 v = xg[q]; x2[2 * q] = v.x; x2[2 * q + 1] = v.y; }
    const u64* wt = (const u64*)sWt;
    float cr[32];
    for (int f0 = 0; f0 < F_N; f0 += 4) {
        u64 a0 = 0, a1 = 0, a2 = 0, a3 = 0;
        const u64* w0 = wt + (f0 + 0) * 32;
        const u64* w1 = wt + (f0 + 1) * 32;
        const u64* w2 = wt + (f0 + 2) * 32;
        const u64* w3 = wt + (f0 + 3) * 32;
#pragma unroll
        for (int k = 0; k < 32; k++) {
            a0 = ffma2(x2[k], w0[k], a0);
            a1 = ffma2(x2[k], w1[k], a1);
            a2 = ffma2(x2[k], w2[k], a2);
            a3 = ffma2(x2[k], w3[k], a3);
        }
        cr[f0 + 0] = fmaxf(hsum(a0) + sb[f0 + 0], 0.0f);
        cr[f0 + 1] = fmaxf(hsum(a1) + sb[f0 + 1], 0.0f);
        cr[f0 + 2] = fmaxf(hsum(a2) + sb[f0 + 2], 0.0f);
        cr[f0 + 3] = fmaxf(hsum(a3) + sb[f0 + 3], 0.0f);
    }
    float4* out4 = (float4*)dst;
#pragma unroll
    for (int q = 0; q < 8; q++)
        out4[q] = make_float4(cr[4 * q], cr[4 * q + 1], cr[4 * q + 2], cr[4 * q + 3]);

    if (!isPath) {
        float4 z4 = make_float4(0.f, 0.f, 0.f, 0.f);
        float4* ag = (float4*)(g_agg + (size_t)row * F_N);
#pragma unroll
        for (int q = 0; q < 8; q++) ag[q] = z4;
        u64 xc[16];
#pragma unroll
        for (int k = 0; k < 16; k++) xc[k] = f2u(cr[2 * k], cr[2 * k + 1]);
        u64* trow = (u64*)(g_table + (size_t)row * 96);
        for (int f0 = 0; f0 < 96; f0 += 2) {
            const u64* wr0 = (const u64*)(sWi1f + (f0 + 0) * 32);
            const u64* wr1 = (const u64*)(sWi1f + (f0 + 1) * 32);
            u64 a0 = 0, a1 = 0;
#pragma unroll
            for (int k = 0; k < 16; k++) {
                a0 = ffma2(xc[k], wr0[k], a0);
                a1 = ffma2(xc[k], wr1[k], a1);
            }
            int gate = f0 >> 5, fin = f0 & 31;
            trow[gate * 16 + (fin >> 1)] = f2u(hsum(a0) + sb1[f0], hsum(a1) + sb1[f0 + 1]);
        }
    }
}

// ---------------- scan6: 128 paths/block, 256 thr = 16(px) x 16(fy), tile 8p x 6o ----------------
// h pairs (f=2fy,2fy+1) register-resident per thread; double-buffered swizzled shf,
// ONE sync per substep; unconditional STS (conflict-4); pipelined table gathers.
__global__ void __launch_bounds__(256, 2) scan6_kernel(const float* __restrict__ Wh,
                                                       const float* __restrict__ bh,
                                                       float* __restrict__ final_out)
{
    __shared__ __align__(16) u64   sww[32 * 48];     // [k][out-pair]: r 0..15, z 16..31, n 32..47
    __shared__ __align__(16) float shf[2][32 * PS];  // double buffer [k][swizzled p]
    __shared__ short slen[STILE];
    __shared__ float sbhn[32];

    int tid = threadIdx.x;
    int s0 = blockIdx.x * STILE;
    int pcount = min(STILE, P_N - s0);

    for (int i = tid; i < 32 * 48; i += 256) {
        int k = i / 48, po = i % 48;
        sww[k * 48 + po] = f2u(Wh[(2 * po) * 32 + k], Wh[(2 * po + 1) * 32 + k]);
    }
    if (tid < 32) sbhn[tid] = bh[64 + tid];
    if (tid < STILE) slen[tid] = (tid < pcount) ? (short)g_len[s0 + tid] : (short)-1;
    if (pcount < STILE) {
        for (int i = tid; i < 32 * PS; i += 256) shf[0][i] = 0.0f;   // zero-fill, then overwrite
        __syncthreads();
    }
    // stage h into buf0 with column swizzle: col(p, f) = (p + 4*((f>>1)&7)) & 127
    for (int i = tid; i < pcount * 8; i += 256) {
        int p = i >> 3, kq = i & 7;
        float4 v = ((const float4*)(g_p + (size_t)s0 * F_N))[i];
        float vv[4] = {v.x, v.y, v.z, v.w};
#pragma unroll
        for (int j = 0; j < 4; j++) {
            int f = 4 * kq + j;
            int col = (p + 4 * ((f >> 1) & 7)) & 127;
            shf[0][f * PS + col] = vv[j];
        }
    }
    __syncthreads();

    int tmax = slen[0];                 // descending sort => block max
    int px = tid >> 4;                  // 0..15
    int fy = tid & 15;                  // 0..15
    int pbase = px * 8;
    int mycol = 4 * (fy & 7);           // swizzle offset for rows 2fy, 2fy+1 (f>>1 == fy)

    // register-resident h pair for this thread's (f, p) ownership
    float hreg[8][2];
#pragma unroll
    for (int p = 0; p < 8; p++) {
        int col = ((pbase + p) + mycol) & 127;
        hreg[p][0] = shf[0][(2 * fy) * PS + col];
        hreg[p][1] = shf[0][(2 * fy + 1) * PS + col];
    }

    int cur = 0;
    const int* idxbase = g_idx;
    for (int t = 0; t <= tmax; t++) {
        const float* bufc = shf[cur];
        float* bufn = shf[cur ^ 1];
        u64 ar[8], az[8], an[8];
#pragma unroll
        for (int p = 0; p < 8; p++) { ar[p] = 0ull; az[p] = 0ull; an[p] = 0ull; }

#pragma unroll 4
        for (int k = 0; k < 32; k++) {
            const u64* wrow = sww + k * 48;
            u64 wr = wrow[fy];
            u64 wz = wrow[16 + fy];
            u64 wn = wrow[32 + fy];
            int off = 4 * ((k >> 1) & 7);
            int c0 = (pbase + off) & 127;
            int c1 = (pbase + off + 4) & 127;
            float4 ha = *(const float4*)(bufc + k * PS + c0);
            float4 hb = *(const float4*)(bufc + k * PS + c1);
            u64 hd[8];
            hd[0] = f2u(ha.x, ha.x); hd[1] = f2u(ha.y, ha.y);
            hd[2] = f2u(ha.z, ha.z); hd[3] = f2u(ha.w, ha.w);
            hd[4] = f2u(hb.x, hb.x); hd[5] = f2u(hb.y, hb.y);
            hd[6] = f2u(hb.z, hb.z); hd[7] = f2u(hb.w, hb.w);
#pragma unroll
            for (int p = 0; p < 8; p++) {
                ar[p] = ffma2(hd[p], wr, ar[p]);
                az[p] = ffma2(hd[p], wz, az[p]);
                an[p] = ffma2(hd[p], wn, an[p]);
            }
        }

        // epilogue: pipelined table gathers; h updates in registers; STS to bufn
        {
            int row0 = min(s0 + pbase, P_N - 1);
            int ch = __ldg(idxbase + (size_t)row0 * L_N + t);
            const u64* tg = (const u64*)(g_table + (size_t)ch * 96);
            u64 pgr = ldg64(tg + fy);
            u64 pgz = ldg64(tg + 16 + fy);
            u64 pgn = ldg64(tg + 32 + fy);
#pragma unroll
            for (int p = 0; p < 8; p++) {
                u64 cgr = pgr, cgz = pgz, cgn = pgn;
                if (p < 7) {
                    int rown = min(s0 + pbase + p + 1, P_N - 1);
                    int chn = __ldg(idxbase + (size_t)rown * L_N + t);
                    const u64* tgn = (const u64*)(g_table + (size_t)chn * 96);
                    pgr = ldg64(tgn + fy);
                    pgz = ldg64(tgn + 16 + fy);
                    pgn = ldg64(tgn + 32 + fy);
                }
                int pp = pbase + p;
                bool active = (t <= slen[pp]);
                float2 gr = u2f(cgr), gz = u2f(cgz), gn = u2f(cgn);
                float2 vr = u2f(ar[p]), vz = u2f(az[p]), vn = u2f(an[p]);
#pragma unroll
                for (int half = 0; half < 2; half++) {
                    int f = 2 * fy + half;
                    float ivr = half ? vr.y : vr.x;
                    float ivz = half ? vz.y : vz.x;
                    float ivn = half ? vn.y : vn.x;
                    float igr = half ? gr.y : gr.x;
                    float igz = half ? gz.y : gz.x;
                    float ign = half ? gn.y : gn.x;
                    float r = fast_sigmoid(igr + ivr);
                    float z = fast_sigmoid(igz + ivz);
                    float n = fast_tanh(ign + r * (ivn + sbhn[f]));
                    float hold = hreg[p][half];
                    hreg[p][half] = active ? (n + z * (hold - n)) : hold;
                }
                int col = (pp + mycol) & 127;
                bufn[(2 * fy) * PS + col]     = hreg[p][0];
                bufn[(2 * fy + 1) * PS + col] = hreg[p][1];
            }
        }
        __syncthreads();
        cur ^= 1;
    }

    // tail: 2 threads per path (kc = feature half) — write back + atomics
    int p = tid & (STILE - 1);
    int kc = tid >> 7;
    if (p < pcount) {
        const float* buff = shf[cur];
        float v[16];
#pragma unroll
        for (int j = 0; j < 16; j++) {
            int f = kc * 16 + j;
            int col = (p + 4 * ((f >> 1) & 7)) & 127;
            v[j] = buff[f * PS + col];
        }
        float4* dst;
        if (final_out) {
            int ord = g_order[s0 + p];
            dst = (float4*)(final_out + (size_t)ord * F_N + kc * 16);
        } else {
            dst = (float4*)(g_p + (size_t)(s0 + p) * F_N + kc * 16);
        }
#pragma unroll
        for (int q = 0; q < 4; q++)
            dst[q] = make_float4(v[4 * q], v[4 * q + 1], v[4 * q + 2], v[4 * q + 3]);
        int ln = slen[p];
#pragma unroll 1
        for (int t = 0; t <= ln; t++) {
            int ch = __ldg(idxbase + (size_t)(s0 + p) * L_N + t);
            float* base = g_agg + (size_t)ch * F_N + kc * 16;
            red_add_v4(base + 0,  make_float4(v[0],  v[1],  v[2],  v[3]));
            red_add_v4(base + 4,  make_float4(v[4],  v[5],  v[6],  v[7]));
            red_add_v4(base + 8,  make_float4(v[8],  v[9],  v[10], v[11]));
            red_add_v4(base + 12, make_float4(v[12], v[13], v[14], v[15]));
        }
    }
}

// ---------------- fused layer2: c = GRU(agg, c); optionally gi1 table ----------------
// 64 rows/block, 256 thr = 16(px) x 16(fy), tile 4p x 6o.
__global__ void __launch_bounds__(256) layer2_kernel(float* __restrict__ c,
                                                     const float* __restrict__ Wi2,
                                                     const float* __restrict__ Wh2,
                                                     const float* __restrict__ bi2,
                                                     const float* __restrict__ bh2,
                                                     const float* __restrict__ Wi1,
                                                     const float* __restrict__ bi1,
                                                     const float* __restrict__ bh1,
                                                     int want_table)
{
    __shared__ __align__(16) u64   swa[32 * 48];     // Wi2 pairs, later Wi1 pairs
    __shared__ __align__(16) u64   swh[32 * 48];     // Wh2 pairs
    __shared__ __align__(16) float sbuf[32 * PS2];   // staging [k][row]: agg -> c -> cnew
    __shared__ float sbi[96];
    __shared__ float sbhn2[32];
    __shared__ float sb1[96];

    int tid = threadIdx.x;
    int s0 = blockIdx.x * L2TILE;
    int rcount = min(L2TILE, C_N - s0);

    for (int i = tid; i < 32 * 48; i += 256) {
        int k = i / 48, po = i % 48;
        swa[k * 48 + po] = f2u(Wi2[(2 * po) * 32 + k], Wi2[(2 * po + 1) * 32 + k]);
        swh[k * 48 + po] = f2u(Wh2[(2 * po) * 32 + k], Wh2[(2 * po + 1) * 32 + k]);
    }
    if (tid < 96) {
        sbi[tid] = bi2[tid] + (tid < 64 ? bh2[tid] : 0.0f);
        sb1[tid] = bi1[tid] + (tid < 64 ? bh1[tid] : 0.0f);
    }
    if (tid < 32) sbhn2[tid] = bh2[64 + tid];
    if (rcount < L2TILE) {
        for (int i = tid; i < 32 * L2TILE; i += 256) {
            int p = i & (L2TILE - 1);
            if (p >= rcount) sbuf[(i >> 6) * PS2 + p] = 0.0f;
        }
    }
    for (int i = tid; i < rcount * 8; i += 256) {
        int p = i >> 3, kq = i & 7;
        float4 v = ((const float4*)(g_agg + (size_t)s0 * F_N))[i];
        sbuf[(4 * kq + 0) * PS2 + p] = v.x;
        sbuf[(4 * kq + 1) * PS2 + p] = v.y;
        sbuf[(4 * kq + 2) * PS2 + p] = v.z;
        sbuf[(4 * kq + 3) * PS2 + p] = v.w;
        ((float4*)(g_agg + (size_t)s0 * F_N))[i] = make_float4(0.f, 0.f, 0.f, 0.f);
    }
    __syncthreads();

    int px = tid >> 4, fy = tid & 15;
    int pbase = px * 4;

    u64 ir[4], iz[4], in_[4];
#pragma unroll
    for (int p = 0; p < 4; p++) { ir[p] = 0ull; iz[p] = 0ull; in_[p] = 0ull; }
#pragma unroll 4
    for (int k = 0; k < 32; k++) {
        const u64* wrow = swa + k * 48;
        u64 wr = wrow[fy];
        u64 wz = wrow[16 + fy];
        u64 wn = wrow[32 + fy];
        float4 ha = *(const float4*)(sbuf + k * PS2 + pbase);
        u64 hd[4];
        hd[0] = f2u(ha.x, ha.x); hd[1] = f2u(ha.y, ha.y);
        hd[2] = f2u(ha.z, ha.z); hd[3] = f2u(ha.w, ha.w);
#pragma unroll
        for (int p = 0; p < 4; p++) {
            ir[p]  = ffma2(hd[p], wr, ir[p]);
            iz[p]  = ffma2(hd[p], wz, iz[p]);
            in_[p] = ffma2(hd[p], wn, in_[p]);
        }
    }
    __syncthreads();

    // restage: sbuf <- c rows; swa <- Wi1 pairs for table phase
    for (int i = tid; i < rcount * 8; i += 256) {
        int p = i >> 3, kq = i & 7;
        float4 v = ((const float4*)(c + (size_t)s0 * F_N))[i];
        sbuf[(4 * kq + 0) * PS2 + p] = v.x;
        sbuf[(4 * kq + 1) * PS2 + p] = v.y;
        sbuf[(4 * kq + 2) * PS2 + p] = v.z;
        sbuf[(4 * kq + 3) * PS2 + p] = v.w;
    }
    if (want_table) {
        for (int i = tid; i < 32 * 48; i += 256) {
            int k = i / 48, po = i % 48;
            swa[k * 48 + po] = f2u(Wi1[(2 * po) * 32 + k], Wi1[(2 * po + 1) * 32 + k]);
        }
    }
    __syncthreads();

    u64 hr_[4], hz_[4], hn_[4];
#pragma unroll
    for (int p = 0; p < 4; p++) { hr_[p] = 0ull; hz_[p] = 0ull; hn_[p] = 0ull; }
#pragma unroll 4
    for (int k = 0; k < 32; k++) {
        const u64* wrow = swh + k * 48;
        u64 wr = wrow[fy];
        u64 wz = wrow[16 + fy];
        u64 wn = wrow[32 + fy];
        float4 ha = *(const float4*)(sbuf + k * PS2 + pbase);
        u64 hd[4];
        hd[0] = f2u(ha.x, ha.x); hd[1] = f2u(ha.y, ha.y);
        hd[2] = f2u(ha.z, ha.z); hd[3] = f2u(ha.w, ha.w);
#pragma unroll
        for (int p = 0; p < 4; p++) {
            hr_[p] = ffma2(hd[p], wr, hr_[p]);
            hz_[p] = ffma2(hd[p], wz, hz_[p]);
            hn_[p] = ffma2(hd[p], wn, hn_[p]);
        }
    }
    __syncthreads();   // k-loop reads done before in-place cnew writes

#pragma unroll
    for (int p = 0; p < 4; p++) {
        int pp = pbase + p;
        if (pp < rcount) {
            int ch = s0 + pp;
            u64* cdst = (u64*)(c + (size_t)ch * F_N);
            float2 vi_r = u2f(ir[p]),  vi_z = u2f(iz[p]),  vi_n = u2f(in_[p]);
            float2 vh_r = u2f(hr_[p]), vh_z = u2f(hz_[p]), vh_n = u2f(hn_[p]);
            float hnew2[2];
#pragma unroll
            for (int half = 0; half < 2; half++) {
                int f = 2 * fy + half;
                float a_ir = half ? vi_r.y : vi_r.x;
                float a_iz = half ? vi_z.y : vi_z.x;
                float a_in = half ? vi_n.y : vi_n.x;
                float a_hr = half ? vh_r.y : vh_r.x;
                float a_hz = half ? vh_z.y : vh_z.x;
                float a_hn = half ? vh_n.y : vh_n.x;
                float r = fast_sigmoid(a_ir + sbi[f] + a_hr);
                float z = fast_sigmoid(a_iz + sbi[32 + f] + a_hz);
                float n = fast_tanh(a_in + sbi[64 + f] + r * (a_hn + sbhn2[f]));
                float hold = sbuf[f * PS2 + pp];
                float hv = n + z * (hold - n);
                hnew2[half] = hv;
                sbuf[f * PS2 + pp] = hv;
            }
            cdst[fy] = f2u(hnew2[0], hnew2[1]);
        }
    }

    if (!want_table) return;
    __syncthreads();   // cnew staged

    u64 tr[4], tz[4], tn[4];
#pragma unroll
    for (int p = 0; p < 4; p++) { tr[p] = 0ull; tz[p] = 0ull; tn[p] = 0ull; }
#pragma unroll 4
    for (int k = 0; k < 32; k++) {
        const u64* wrow = swa + k * 48;
        u64 wr = wrow[fy];
        u64 wz = wrow[16 + fy];
        u64 wn = wrow[32 + fy];
        float4 ha = *(const float4*)(sbuf + k * PS2 + pbase);
        u64 hd[4];
        hd[0] = f2u(ha.x, ha.x); hd[1] = f2u(ha.y, ha.y);
        hd[2] = f2u(ha.z, ha.z); hd[3] = f2u(ha.w, ha.w);
#pragma unroll
        for (int p = 0; p < 4; p++) {
            tr[p] = ffma2(hd[p], wr, tr[p]);
            tz[p] = ffma2(hd[p], wz, tz[p]);
            tn[p] = ffma2(hd[p], wn, tn[p]);
        }
    }
#pragma unroll
    for (int p = 0; p < 4; p++) {
        int pp = pbase + p;
        if (pp < rcount) {
            u64* trow = (u64*)(g_table + (size_t)(s0 + pp) * 96);
            float2 a0 = u2f(tr[p]), a1 = u2f(tz[p]), a2 = u2f(tn[p]);
            trow[fy]      = f2u(a0.x + sb1[2 * fy],      a0.y + sb1[2 * fy + 1]);
            trow[16 + fy] = f2u(a1.x + sb1[32 + 2 * fy], a1.y + sb1[32 + 2 * fy + 1]);
            trow[32 + fy] = f2u(a2.x + sb1[64 + 2 * fy], a2.y + sb1[64 + 2 * fy + 1]);
        }
    }
}

// ---------------- launch ----------------
extern "C" void kernel_launch(void* const* d_in, const int* in_sizes, int n_in,
                              void* d_out, int out_size)
{
    const float* path_raw    = (const float*)d_in[0];
    const float* channel_raw = (const float*)d_in[1];
    const int*   pci         = (const int*)d_in[2];
    const int*   plen        = (const int*)d_in[3];
    // d_in[4] = num_steps (constant 5)
    const float* Wp  = (const float*)d_in[5];
    const float* bp  = (const float*)d_in[6];
    const float* Wc  = (const float*)d_in[7];
    const float* bc  = (const float*)d_in[8];
    const float* Wi1 = (const float*)d_in[9];
    const float* Wh1 = (const float*)d_in[10];
    const float* bi1 = (const float*)d_in[11];
    const float* bh1 = (const float*)d_in[12];
    const float* Wi2 = (const float*)d_in[13];
    const float* Wh2 = (const float*)d_in[14];
    const float* bi2 = (const float*)d_in[15];
    const float* bh2 = (const float*)d_in[16];

    float* outp = (float*)d_out;
    float* c    = outp + (size_t)P_N * F_N;

    int gridScan = (P_N + STILE - 1) / STILE;     // 1563
    int gridL2   = (C_N + L2TILE - 1) / L2TILE;   // 782

    hist_prefix_kernel<<<PB_BLOCKS, 256>>>(plen);
    scatter_kernel<<<PB_BLOCKS, 256>>>(plen);
    buildinit_gi_kernel<<<PB_BLOCKS + CB_BLOCKS, 256>>>(plen, pci, path_raw, channel_raw,
                                                        Wp, bp, Wc, bc, Wi1, bi1, bh1, c);
    for (int st = 0; st < NSTEPS; st++) {
        scan6_kernel<<<gridScan, 256>>>(Wh1, bh1, (st == NSTEPS - 1) ? outp : nullptr);
        layer2_kernel<<<gridL2, 256>>>(c, Wi2, Wh2, bi2, bh2, Wi1, bi1, bh1,
                                       (st < NSTEPS - 1) ? 1 : 0);
    }
}

// round 10
// speedup vs baseline: 1.5785x; 1.0043x over previous
#include <cuda_runtime.h>

#define P_N 200000
#define C_N 50000
#define L_N 8
#define F_N 32
#define DIN 64
#define NSTEPS 5

#define PB_BLOCKS ((P_N + 255) / 256)   // 782
#define CB_BLOCKS ((C_N + 255) / 256)   // 196

#define STILE 128                       // scan paths per block
#define SROW 260                        // floats per h-pair row (128 float2 + pad)
#define L2TILE 64
#define PS2 68                          // float stride for layer2 staging

typedef unsigned long long u64;

// ---------------- device scratch ----------------
__device__ float g_p[(size_t)P_N * F_N];
__device__ int   g_order[P_N];
__device__ int   g_idx[(size_t)P_N * L_N];
__device__ int   g_len[P_N];
__device__ float g_agg[(size_t)C_N * F_N];
__device__ float g_table[(size_t)C_N * 96];
__device__ int   g_cnt[16];
__device__ int   g_blkhist[PB_BLOCKS * 8];
__device__ int   g_done;

// ---------------- helpers ----------------
__device__ __forceinline__ u64 ffma2(u64 a, u64 b, u64 c) {
    u64 d;
    asm("fma.rn.f32x2 %0, %1, %2, %3;" : "=l"(d) : "l"(a), "l"(b), "l"(c));
    return d;
}
__device__ __forceinline__ float2 u2f(u64 v) {
    float2 r;
    asm("mov.b64 {%0,%1}, %2;" : "=f"(r.x), "=f"(r.y) : "l"(v));
    return r;
}
__device__ __forceinline__ u64 f2u(float a, float b) {
    u64 r;
    asm("mov.b64 %0, {%1,%2};" : "=l"(r) : "f"(a), "f"(b));
    return r;
}
__device__ __forceinline__ float hsum(u64 v) { float2 f = u2f(v); return f.x + f.y; }

__device__ __forceinline__ float tanh_ap(float x) {
    float y;
    asm("tanh.approx.f32 %0, %1;" : "=f"(y) : "f"(x));
    return y;
}
__device__ __forceinline__ float fast_sigmoid(float v) {
    return fmaf(0.5f, tanh_ap(0.5f * v), 0.5f);
}
__device__ __forceinline__ float fast_tanh(float v) { return tanh_ap(v); }

__device__ __forceinline__ void red_add_v4(float* p, float4 v) {
    asm volatile("red.global.add.v4.f32 [%0], {%1,%2,%3,%4};"
                 :: "l"(p), "f"(v.x), "f"(v.y), "f"(v.z), "f"(v.w) : "memory");
}
__device__ __forceinline__ u64 ldg64(const u64* p) {
    u64 v;
    asm("ld.global.nc.b64 %0, [%1];" : "=l"(v) : "l"(p));
    return v;
}

// ---------------- fused hist + prefix (last-block-done) ----------------
__global__ void __launch_bounds__(256) hist_prefix_kernel(const int* __restrict__ plen) {
    __shared__ int lh[8];
    __shared__ int slast;
    int tid = threadIdx.x;
    if (tid < 8) lh[tid] = 0;
    __syncthreads();
    int i = blockIdx.x * 256 + tid;
    if (i < P_N) {
        int b = plen[i]; b = b < 0 ? 0 : (b > 7 ? 7 : b);
        atomicAdd(&lh[b], 1);
    }
    __syncthreads();
    if (tid < 8) g_blkhist[blockIdx.x * 8 + tid] = lh[tid];
    __threadfence();
    if (tid == 0) {
        int t = atomicAdd(&g_done, 1);
        slast = (t == gridDim.x - 1) ? 1 : 0;
    }
    __syncthreads();
    if (slast) {
        __threadfence();
        int local[8] = {0, 0, 0, 0, 0, 0, 0, 0};
        for (int j = tid; j < PB_BLOCKS; j += 256) {
#pragma unroll
            for (int b = 0; b < 8; b++) local[b] += g_blkhist[j * 8 + b];
        }
        if (tid < 8) lh[tid] = 0;
        __syncthreads();
#pragma unroll
        for (int b = 0; b < 8; b++) atomicAdd(&lh[b], local[b]);
        __syncthreads();
        if (tid == 0) {
            int acc = 0;
#pragma unroll
            for (int b = 7; b >= 0; b--) { int cv = lh[b]; g_cnt[b] = acc; acc += cv; }
            g_done = 0;
        }
    }
}

__global__ void __launch_bounds__(256) scatter_kernel(const int* __restrict__ plen) {
    int i = blockIdx.x * 256 + threadIdx.x;
    if (i < P_N) {
        int b = plen[i]; b = b < 0 ? 0 : (b > 7 ? 7 : b);
        int pos = atomicAdd(&g_cnt[b], 1);
        g_order[pos] = i;
    }
}

// ---------------- fused build(paths) + initc + step0 gi1 table (channels) ----------------
__global__ void __launch_bounds__(256) buildinit_gi_kernel(const int* __restrict__ plen,
                                                           const int* __restrict__ pci,
                                                           const float* __restrict__ praw,
                                                           const float* __restrict__ craw,
                                                           const float* __restrict__ Wp,
                                                           const float* __restrict__ bp,
                                                           const float* __restrict__ Wc,
                                                           const float* __restrict__ bc,
                                                           const float* __restrict__ Wi1,
                                                           const float* __restrict__ bi1,
                                                           const float* __restrict__ bh1,
                                                           float* __restrict__ c)
{
    __shared__ __align__(16) float sWt[F_N * DIN];
    __shared__ float sb[F_N];
    __shared__ __align__(16) float sWi1f[96 * 32];
    __shared__ float sb1[96];
    int tid = threadIdx.x;
    bool isPath = blockIdx.x < PB_BLOCKS;
    const float* W = isPath ? Wp : Wc;
    const float* b = isPath ? bp : bc;
    for (int i = tid; i < DIN * F_N; i += 256) {
        int d = i >> 5, f = i & 31;
        sWt[f * DIN + d] = W[i];
    }
    if (tid < F_N) sb[tid] = b[tid];
    if (!isPath) {
        for (int i = tid; i < 96 * 32; i += 256) sWi1f[i] = Wi1[i];
        if (tid < 96) sb1[tid] = bi1[tid] + (tid < 64 ? bh1[tid] : 0.0f);
    }
    __syncthreads();

    int row, srcrow;
    const float* xsrc;
    float* dst;
    if (isPath) {
        row = blockIdx.x * 256 + tid;
        if (row >= P_N) return;
        srcrow = g_order[row];
        g_len[row] = plen[srcrow];
        const int4* si = (const int4*)(pci + (size_t)srcrow * L_N);
        int4* di = (int4*)(g_idx + (size_t)row * L_N);
        di[0] = si[0]; di[1] = si[1];
        xsrc = praw;
        dst = g_p + (size_t)row * F_N;
    } else {
        row = (blockIdx.x - PB_BLOCKS) * 256 + tid;
        if (row >= C_N) return;
        srcrow = row;
        xsrc = craw;
        dst = c + (size_t)row * F_N;
    }

    u64 x2[32];
    const ulonglong2* xg = (const ulonglong2*)(xsrc + (size_t)srcrow * DIN);
#pragma unroll
    for (int q = 0; q < 16; q++) { ulonglong2 v = xg[q]; x2[2 * q] = v.x; x2[2 * q + 1] = v.y; }
    const u64* wt = (const u64*)sWt;
    float cr[32];
    for (int f0 = 0; f0 < F_N; f0 += 4) {
        u64 a0 = 0, a1 = 0, a2 = 0, a3 = 0;
        const u64* w0 = wt + (f0 + 0) * 32;
        const u64* w1 = wt + (f0 + 1) * 32;
        const u64* w2 = wt + (f0 + 2) * 32;
        const u64* w3 = wt + (f0 + 3) * 32;
#pragma unroll
        for (int k = 0; k < 32; k++) {
            a0 = ffma2(x2[k], w0[k], a0);
            a1 = ffma2(x2[k], w1[k], a1);
            a2 = ffma2(x2[k], w2[k], a2);
            a3 = ffma2(x2[k], w3[k], a3);
        }
        cr[f0 + 0] = fmaxf(hsum(a0) + sb[f0 + 0], 0.0f);
        cr[f0 + 1] = fmaxf(hsum(a1) + sb[f0 + 1], 0.0f);
        cr[f0 + 2] = fmaxf(hsum(a2) + sb[f0 + 2], 0.0f);
        cr[f0 + 3] = fmaxf(hsum(a3) + sb[f0 + 3], 0.0f);
    }
    float4* out4 = (float4*)dst;
#pragma unroll
    for (int q = 0; q < 8; q++)
        out4[q] = make_float4(cr[4 * q], cr[4 * q + 1], cr[4 * q + 2], cr[4 * q + 3]);

    if (!isPath) {
        float4 z4 = make_float4(0.f, 0.f, 0.f, 0.f);
        float4* ag = (float4*)(g_agg + (size_t)row * F_N);
#pragma unroll
        for (int q = 0; q < 8; q++) ag[q] = z4;
        u64 xc[16];
#pragma unroll
        for (int k = 0; k < 16; k++) xc[k] = f2u(cr[2 * k], cr[2 * k + 1]);
        u64* trow = (u64*)(g_table + (size_t)row * 96);
        for (int f0 = 0; f0 < 96; f0 += 2) {
            const u64* wr0 = (const u64*)(sWi1f + (f0 + 0) * 32);
            const u64* wr1 = (const u64*)(sWi1f + (f0 + 1) * 32);
            u64 a0 = 0, a1 = 0;
#pragma unroll
            for (int k = 0; k < 16; k++) {
                a0 = ffma2(xc[k], wr0[k], a0);
                a1 = ffma2(xc[k], wr1[k], a1);
            }
            int gate = f0 >> 5, fin = f0 & 31;
            trow[gate * 16 + (fin >> 1)] = f2u(hsum(a0) + sb1[f0], hsum(a1) + sb1[f0 + 1]);
        }
    }
}

// ---------------- scan7: float2-row h layout, 2-way STS, reg-resident h ----------------
// 128 paths/block, 256 thr = 16(px) x 16(fy), tile 8 paths x 6 outs.
// shf row j (0..15) holds (h[2j], h[2j+1]) pairs; row stride 260 floats (mod 32 = 4).
__global__ void __launch_bounds__(256, 2) scan7_kernel(const float* __restrict__ Wh,
                                                       const float* __restrict__ bh,
                                                       float* __restrict__ final_out)
{
    __shared__ __align__(16) u64   sww[32 * 48];       // [k][out-pair]
    __shared__ __align__(16) float shf[2][16 * SROW];  // double buffer
    __shared__ short slen[STILE];
    __shared__ float sbhn[32];

    int tid = threadIdx.x;
    int s0 = blockIdx.x * STILE;
    int pcount = min(STILE, P_N - s0);

    for (int i = tid; i < 32 * 48; i += 256) {
        int k = i / 48, po = i % 48;
        sww[k * 48 + po] = f2u(Wh[(2 * po) * 32 + k], Wh[(2 * po + 1) * 32 + k]);
    }
    if (tid < 32) sbhn[tid] = bh[64 + tid];
    if (tid < STILE) slen[tid] = (tid < pcount) ? (short)g_len[s0 + tid] : (short)-1;
    if (pcount < STILE) {
        for (int i = tid; i < 16 * SROW; i += 256) shf[0][i] = 0.0f;
        __syncthreads();
    }
    // stage h: row f>>1, float col 2p + (f&1)
    for (int i = tid; i < pcount * 8; i += 256) {
        int p = i >> 3, kq = i & 7;
        float4 v = ((const float4*)(g_p + (size_t)s0 * F_N))[i];
        float* r0 = &shf[0][(2 * kq) * SROW + 2 * p];
        r0[0] = v.x; r0[1] = v.y;
        float* r1 = &shf[0][(2 * kq + 1) * SROW + 2 * p];
        r1[0] = v.z; r1[1] = v.w;
    }
    __syncthreads();

    int tmax = slen[0];                 // descending sort => block max
    int px = tid >> 4;                  // 0..15
    int fy = tid & 15;                  // 0..15
    int pbase = px * 8;

    // register-resident h pair (features 2fy, 2fy+1) for 8 owned paths
    float hreg[8][2];
#pragma unroll
    for (int p = 0; p < 8; p++) {
        hreg[p][0] = shf[0][fy * SROW + 2 * (pbase + p)];
        hreg[p][1] = shf[0][fy * SROW + 2 * (pbase + p) + 1];
    }

    int cur = 0;
    const int* idxbase = g_idx;
    for (int t = 0; t <= tmax; t++) {
        const float* bufc = shf[cur];
        float* bufn = shf[cur ^ 1];
        u64 ar[8], az[8], an[8];
#pragma unroll
        for (int p = 0; p < 8; p++) { ar[p] = 0ull; az[p] = 0ull; an[p] = 0ull; }

#pragma unroll 4
        for (int j = 0; j < 16; j++) {          // k-pair: k = 2j, 2j+1
            const u64* w0 = sww + (2 * j) * 48;
            const u64* w1 = sww + (2 * j + 1) * 48;
            u64 wr0 = w0[fy], wz0 = w0[16 + fy], wn0 = w0[32 + fy];
            u64 wr1 = w1[fy], wz1 = w1[16 + fy], wn1 = w1[32 + fy];
            const float4* hq = (const float4*)(bufc + j * SROW + 2 * pbase);
            float4 q0 = hq[0], q1 = hq[1], q2 = hq[2], q3 = hq[3];
            float qe[8] = {q0.x, q0.z, q1.x, q1.z, q2.x, q2.z, q3.x, q3.z};
            float qo[8] = {q0.y, q0.w, q1.y, q1.w, q2.y, q2.w, q3.y, q3.w};
#pragma unroll
            for (int p = 0; p < 8; p++) {
                u64 he = f2u(qe[p], qe[p]);
                ar[p] = ffma2(he, wr0, ar[p]);
                az[p] = ffma2(he, wz0, az[p]);
                an[p] = ffma2(he, wn0, an[p]);
                u64 ho = f2u(qo[p], qo[p]);
                ar[p] = ffma2(ho, wr1, ar[p]);
                az[p] = ffma2(ho, wz1, az[p]);
                an[p] = ffma2(ho, wn1, an[p]);
            }
        }

        // epilogue: pipelined table gathers; reg h updates; STS.64 (2-way) to bufn
        {
            int row0 = min(s0 + pbase, P_N - 1);
            int ch = __ldg(idxbase + (size_t)row0 * L_N + t);
            const u64* tg = (const u64*)(g_table + (size_t)ch * 96);
            u64 pgr = ldg64(tg + fy);
            u64 pgz = ldg64(tg + 16 + fy);
            u64 pgn = ldg64(tg + 32 + fy);
#pragma unroll
            for (int p = 0; p < 8; p++) {
                u64 cgr = pgr, cgz = pgz, cgn = pgn;
                if (p < 7) {
                    int rown = min(s0 + pbase + p + 1, P_N - 1);
                    int chn = __ldg(idxbase + (size_t)rown * L_N + t);
                    const u64* tgn = (const u64*)(g_table + (size_t)chn * 96);
                    pgr = ldg64(tgn + fy);
                    pgz = ldg64(tgn + 16 + fy);
                    pgn = ldg64(tgn + 32 + fy);
                }
                int pp = pbase + p;
                bool active = (t <= slen[pp]);
                float2 gr = u2f(cgr), gz = u2f(cgz), gn = u2f(cgn);
                float2 vr = u2f(ar[p]), vz = u2f(az[p]), vn = u2f(an[p]);
#pragma unroll
                for (int half = 0; half < 2; half++) {
                    int f = 2 * fy + half;
                    float ivr = half ? vr.y : vr.x;
                    float ivz = half ? vz.y : vz.x;
                    float ivn = half ? vn.y : vn.x;
                    float igr = half ? gr.y : gr.x;
                    float igz = half ? gz.y : gz.x;
                    float ign = half ? gn.y : gn.x;
                    float r = fast_sigmoid(igr + ivr);
                    float z = fast_sigmoid(igz + ivz);
                    float n = fast_tanh(ign + r * (ivn + sbhn[f]));
                    float hold = hreg[p][half];
                    hreg[p][half] = active ? (n + z * (hold - n)) : hold;
                }
                *(float2*)(bufn + fy * SROW + 2 * pp) = make_float2(hreg[p][0], hreg[p][1]);
            }
        }
        __syncthreads();
        cur ^= 1;
    }

    // tail: 2 threads per path (kc = feature half) — write back + atomics
    int p = tid & (STILE - 1);
    int kc = tid >> 7;
    if (p < pcount) {
        const float* buff = shf[cur];
        float v[16];
#pragma unroll
        for (int j = 0; j < 16; j++) {
            int f = kc * 16 + j;
            v[j] = buff[(f >> 1) * SROW + 2 * p + (f & 1)];
        }
        float4* dst;
        if (final_out) {
            int ord = g_order[s0 + p];
            dst = (float4*)(final_out + (size_t)ord * F_N + kc * 16);
        } else {
            dst = (float4*)(g_p + (size_t)(s0 + p) * F_N + kc * 16);
        }
#pragma unroll
        for (int q = 0; q < 4; q++)
            dst[q] = make_float4(v[4 * q], v[4 * q + 1], v[4 * q + 2], v[4 * q + 3]);
        int ln = slen[p];
#pragma unroll 1
        for (int t = 0; t <= ln; t++) {
            int ch = __ldg(idxbase + (size_t)(s0 + p) * L_N + t);
            float* base = g_agg + (size_t)ch * F_N + kc * 16;
            red_add_v4(base + 0,  make_float4(v[0],  v[1],  v[2],  v[3]));
            red_add_v4(base + 4,  make_float4(v[4],  v[5],  v[6],  v[7]));
            red_add_v4(base + 8,  make_float4(v[8],  v[9],  v[10], v[11]));
            red_add_v4(base + 12, make_float4(v[12], v[13], v[14], v[15]));
        }
    }
}

// ---------------- layer2f: FUSED gi2+gh2 k-loop, then epilogue, then gi1 table ----------------
// 64 rows/block, 256 thr = 16(px) x 16(fy), tile 4 rows x 6 outs per accumulator set.
__global__ void __launch_bounds__(256) layer2f_kernel(float* __restrict__ c,
                                                      const float* __restrict__ Wi2,
                                                      const float* __restrict__ Wh2,
                                                      const float* __restrict__ bi2,
                                                      const float* __restrict__ bh2,
                                                      const float* __restrict__ Wi1,
                                                      const float* __restrict__ bi1,
                                                      const float* __restrict__ bh1,
                                                      int want_table)
{
    __shared__ __align__(16) u64   swa[32 * 48];     // Wi2 pairs, later Wi1 pairs
    __shared__ __align__(16) u64   swh[32 * 48];     // Wh2 pairs
    __shared__ __align__(16) float sagg[32 * PS2];   // agg staging -> cnew staging
    __shared__ __align__(16) float sc[32 * PS2];     // c staging (hold values)
    __shared__ float sbi[96];
    __shared__ float sbhn2[32];
    __shared__ float sb1[96];

    int tid = threadIdx.x;
    int s0 = blockIdx.x * L2TILE;
    int rcount = min(L2TILE, C_N - s0);

    for (int i = tid; i < 32 * 48; i += 256) {
        int k = i / 48, po = i % 48;
        swa[k * 48 + po] = f2u(Wi2[(2 * po) * 32 + k], Wi2[(2 * po + 1) * 32 + k]);
        swh[k * 48 + po] = f2u(Wh2[(2 * po) * 32 + k], Wh2[(2 * po + 1) * 32 + k]);
    }
    if (tid < 96) {
        sbi[tid] = bi2[tid] + (tid < 64 ? bh2[tid] : 0.0f);
        sb1[tid] = bi1[tid] + (tid < 64 ? bh1[tid] : 0.0f);
    }
    if (tid < 32) sbhn2[tid] = bh2[64 + tid];
    if (rcount < L2TILE) {
        for (int i = tid; i < 32 * L2TILE; i += 256) {
            int p = i & (L2TILE - 1);
            if (p >= rcount) { sagg[(i >> 6) * PS2 + p] = 0.0f; sc[(i >> 6) * PS2 + p] = 0.0f; }
        }
    }
    for (int i = tid; i < rcount * 8; i += 256) {
        int p = i >> 3, kq = i & 7;
        float4 va = ((const float4*)(g_agg + (size_t)s0 * F_N))[i];
        sagg[(4 * kq + 0) * PS2 + p] = va.x;
        sagg[(4 * kq + 1) * PS2 + p] = va.y;
        sagg[(4 * kq + 2) * PS2 + p] = va.z;
        sagg[(4 * kq + 3) * PS2 + p] = va.w;
        ((float4*)(g_agg + (size_t)s0 * F_N))[i] = make_float4(0.f, 0.f, 0.f, 0.f);
        float4 vc = ((const float4*)(c + (size_t)s0 * F_N))[i];
        sc[(4 * kq + 0) * PS2 + p] = vc.x;
        sc[(4 * kq + 1) * PS2 + p] = vc.y;
        sc[(4 * kq + 2) * PS2 + p] = vc.z;
        sc[(4 * kq + 3) * PS2 + p] = vc.w;
    }
    __syncthreads();

    int px = tid >> 4, fy = tid & 15;
    int pbase = px * 4;

    // fused k-loop: gi2 (from sagg) and gh2 (from sc) accumulators together
    u64 ir[4], iz[4], in_[4], hr_[4], hz_[4], hn_[4];
#pragma unroll
    for (int p = 0; p < 4; p++) {
        ir[p] = 0ull; iz[p] = 0ull; in_[p] = 0ull;
        hr_[p] = 0ull; hz_[p] = 0ull; hn_[p] = 0ull;
    }
#pragma unroll 4
    for (int k = 0; k < 32; k++) {
        const u64* wA = swa + k * 48;
        const u64* wH = swh + k * 48;
        u64 war = wA[fy], waz = wA[16 + fy], wan = wA[32 + fy];
        u64 whr = wH[fy], whz = wH[16 + fy], whn = wH[32 + fy];
        float4 va = *(const float4*)(sagg + k * PS2 + pbase);
        float4 vc = *(const float4*)(sc + k * PS2 + pbase);
        float av[4] = {va.x, va.y, va.z, va.w};
        float cv[4] = {vc.x, vc.y, vc.z, vc.w};
#pragma unroll
        for (int p = 0; p < 4; p++) {
            u64 da = f2u(av[p], av[p]);
            ir[p]  = ffma2(da, war, ir[p]);
            iz[p]  = ffma2(da, waz, iz[p]);
            in_[p] = ffma2(da, wan, in_[p]);
            u64 dc = f2u(cv[p], cv[p]);
            hr_[p] = ffma2(dc, whr, hr_[p]);
            hz_[p] = ffma2(dc, whz, hz_[p]);
            hn_[p] = ffma2(dc, whn, hn_[p]);
        }
    }

    // epilogue: cnew in registers, global write (reads sc; no smem writes yet)
    float hn2[4][2];
#pragma unroll
    for (int p = 0; p < 4; p++) {
        int pp = pbase + p;
        if (pp < rcount) {
            int ch = s0 + pp;
            u64* cdst = (u64*)(c + (size_t)ch * F_N);
            float2 vi_r = u2f(ir[p]),  vi_z = u2f(iz[p]),  vi_n = u2f(in_[p]);
            float2 vh_r = u2f(hr_[p]), vh_z = u2f(hz_[p]), vh_n = u2f(hn_[p]);
#pragma unroll
            for (int half = 0; half < 2; half++) {
                int f = 2 * fy + half;
                float a_ir = half ? vi_r.y : vi_r.x;
                float a_iz = half ? vi_z.y : vi_z.x;
                float a_in = half ? vi_n.y : vi_n.x;
                float a_hr = half ? vh_r.y : vh_r.x;
                float a_hz = half ? vh_z.y : vh_z.x;
                float a_hn = half ? vh_n.y : vh_n.x;
                float r = fast_sigmoid(a_ir + sbi[f] + a_hr);
                float z = fast_sigmoid(a_iz + sbi[32 + f] + a_hz);
                float n = fast_tanh(a_in + sbi[64 + f] + r * (a_hn + sbhn2[f]));
                float hold = sc[f * PS2 + pp];
                hn2[p][half] = n + z * (hold - n);
            }
            cdst[fy] = f2u(hn2[p][0], hn2[p][1]);
        }
    }

    if (!want_table) return;
    __syncthreads();   // all k-loop + epilogue smem reads done before overwrites

    // restage: sagg <- cnew (from registers), swa <- Wi1 pairs
#pragma unroll
    for (int p = 0; p < 4; p++) {
        int pp = pbase + p;
        if (pp < rcount) {
            sagg[(2 * fy) * PS2 + pp]     = hn2[p][0];
            sagg[(2 * fy + 1) * PS2 + pp] = hn2[p][1];
        }
    }
    for (int i = tid; i < 32 * 48; i += 256) {
        int k = i / 48, po = i % 48;
        swa[k * 48 + po] = f2u(Wi1[(2 * po) * 32 + k], Wi1[(2 * po + 1) * 32 + k]);
    }
    __syncthreads();

    u64 tr[4], tz[4], tn[4];
#pragma unroll
    for (int p = 0; p < 4; p++) { tr[p] = 0ull; tz[p] = 0ull; tn[p] = 0ull; }
#pragma unroll 4
    for (int k = 0; k < 32; k++) {
        const u64* wrow = swa + k * 48;
        u64 wr = wrow[fy];
        u64 wz = wrow[16 + fy];
        u64 wn = wrow[32 + fy];
        float4 ha = *(const float4*)(sagg + k * PS2 + pbase);
        float hv[4] = {ha.x, ha.y, ha.z, ha.w};
#pragma unroll
        for (int p = 0; p < 4; p++) {
            u64 hd = f2u(hv[p], hv[p]);
            tr[p] = ffma2(hd, wr, tr[p]);
            tz[p] = ffma2(hd, wz, tz[p]);
            tn[p] = ffma2(hd, wn, tn[p]);
        }
    }
#pragma unroll
    for (int p = 0; p < 4; p++) {
        int pp = pbase + p;
        if (pp < rcount) {
            u64* trow = (u64*)(g_table + (size_t)(s0 + pp) * 96);
            float2 a0 = u2f(tr[p]), a1 = u2f(tz[p]), a2 = u2f(tn[p]);
            trow[fy]      = f2u(a0.x + sb1[2 * fy],      a0.y + sb1[2 * fy + 1]);
            trow[16 + fy] = f2u(a1.x + sb1[32 + 2 * fy], a1.y + sb1[32 + 2 * fy + 1]);
            trow[32 + fy] = f2u(a2.x + sb1[64 + 2 * fy], a2.y + sb1[64 + 2 * fy + 1]);
        }
    }
}

// ---------------- launch ----------------
extern "C" void kernel_launch(void* const* d_in, const int* in_sizes, int n_in,
                              void* d_out, int out_size)
{
    const float* path_raw    = (const float*)d_in[0];
    const float* channel_raw = (const float*)d_in[1];
    const int*   pci         = (const int*)d_in[2];
    const int*   plen        = (const int*)d_in[3];
    // d_in[4] = num_steps (constant 5)
    const float* Wp  = (const float*)d_in[5];
    const float* bp  = (const float*)d_in[6];
    const float* Wc  = (const float*)d_in[7];
    const float* bc  = (const float*)d_in[8];
    const float* Wi1 = (const float*)d_in[9];
    const float* Wh1 = (const float*)d_in[10];
    const float* bi1 = (const float*)d_in[11];
    const float* bh1 = (const float*)d_in[12];
    const float* Wi2 = (const float*)d_in[13];
    const float* Wh2 = (const float*)d_in[14];
    const float* bi2 = (const float*)d_in[15];
    const float* bh2 = (const float*)d_in[16];

    float* outp = (float*)d_out;
    float* c    = outp + (size_t)P_N * F_N;

    int gridScan = (P_N + STILE - 1) / STILE;     // 1563
    int gridL2   = (C_N + L2TILE - 1) / L2TILE;   // 782

    hist_prefix_kernel<<<PB_BLOCKS, 256>>>(plen);
    scatter_kernel<<<PB_BLOCKS, 256>>>(plen);
    buildinit_gi_kernel<<<PB_BLOCKS + CB_BLOCKS, 256>>>(plen, pci, path_raw, channel_raw,
                                                        Wp, bp, Wc, bc, Wi1, bi1, bh1, c);
    for (int st = 0; st < NSTEPS; st++) {
        scan7_kernel<<<gridScan, 256>>>(Wh1, bh1, (st == NSTEPS - 1) ? outp : nullptr);
        layer2f_kernel<<<gridL2, 256>>>(c, Wi2, Wh2, bi2, bh2, Wi1, bi1, bh1,
                                        (st < NSTEPS - 1) ? 1 : 0);
    }
}